// round 4
// baseline (speedup 1.0000x reference)
#include <cuda_runtime.h>
#include <cstdint>
#include <math.h>

// ---------------- problem constants ----------------
#define HH 128
#define GG 512
#define MAXN 50000
#define NHH (MAXN * HH)

// ---------------- device scratch ----------------
__device__ float g_xh[NHH];
__device__ float g_agg1[NHH];
__device__ float g_agg2[NHH];
__device__ float g_c[NHH];
__device__ float g_ha[NHH];
__device__ float g_hb[NHH];
__device__ float g_on[NHH];
__device__ float g_gsum[GG * HH];
__device__ float g_gsq[GG * HH];
__device__ float g_gcnt[GG];
__device__ float g_w12a_hi[128 * 147];
__device__ float g_w12a_lo[128 * 147];
__device__ float g_w12b_hi[128 * 21];
__device__ float g_w12b_lo[128 * 21];

// ---------------- tf32 helpers ----------------
__device__ __forceinline__ void split_tf32(float x, uint32_t& hi, uint32_t& lo) {
    asm("cvt.rna.tf32.f32 %0, %1;" : "=r"(hi) : "f"(x));
    float r = x - __uint_as_float(hi);
    asm("cvt.rna.tf32.f32 %0, %1;" : "=r"(lo) : "f"(r));
}
__device__ __forceinline__ float2 split2(float x) {
    uint32_t hi, lo;
    split_tf32(x, hi, lo);
    return make_float2(__uint_as_float(hi), __uint_as_float(lo));
}

__device__ __forceinline__ void mma8(float* d, uint32_t a0, uint32_t a1, uint32_t a2,
                                     uint32_t a3, uint32_t b0, uint32_t b1) {
    asm volatile(
        "mma.sync.aligned.m16n8k8.row.col.f32.tf32.tf32.f32 "
        "{%0,%1,%2,%3}, {%4,%5,%6,%7}, {%8,%9}, {%0,%1,%2,%3};\n"
        : "+f"(d[0]), "+f"(d[1]), "+f"(d[2]), "+f"(d[3])
        : "r"(a0), "r"(a1), "r"(a2), "r"(a3), "r"(b0), "r"(b1));
}

// issue the 3xTF32 triple for one (A-frag, B-frag) pair
__device__ __forceinline__ void mma3(float* d, const float2& a0, const float2& a1,
                                     const float2& a2, const float2& a3,
                                     uint32_t bh0, uint32_t bh1, uint32_t bl0, uint32_t bl1) {
    uint32_t ah0 = __float_as_uint(a0.x), al0 = __float_as_uint(a0.y);
    uint32_t ah1 = __float_as_uint(a1.x), al1 = __float_as_uint(a1.y);
    uint32_t ah2 = __float_as_uint(a2.x), al2 = __float_as_uint(a2.y);
    uint32_t ah3 = __float_as_uint(a3.x), al3 = __float_as_uint(a3.y);
    mma8(d, al0, al1, al2, al3, bh0, bh1);
    mma8(d, ah0, ah1, ah2, ah3, bl0, bl1);
    mma8(d, ah0, ah1, ah2, ah3, bh0, bh1);
}

// ---------------- misc kernels ----------------
__global__ void k_zero(int sel, int n) {
    int i = blockIdx.x * blockDim.x + threadIdx.x;
    if (sel == 0) { if (i < n) g_agg1[i] = 0.f; }
    else if (sel == 1) { if (i < n) g_agg2[i] = 0.f; }
    else {
        if (i < GG * HH) { g_gsum[i] = 0.f; g_gsq[i] = 0.f; }
        if (i < GG) g_gcnt[i] = 0.f;
    }
}

// W12[k][n] = sum_m W1[k][m] * W2[m][n]; store split n-major: out[n*F + k]
template <int F>
__global__ void k_w12(const float* __restrict__ W1, const float* __restrict__ W2,
                      float* __restrict__ ohi, float* __restrict__ olo) {
    int k = blockIdx.x, n = threadIdx.x;
    float acc = 0.f;
    for (int m = 0; m < 64; m++) acc += W1[k * 64 + m] * W2[m * 128 + n];
    uint32_t hi, lo;
    split_tf32(acc, hi, lo);
    ohi[n * F + k] = __uint_as_float(hi);
    olo[n * F + k] = __uint_as_float(lo);
}

// ---------------- tensor-core node GEMM (512 threads) ----------------
// out = [swish](A @ Wa [+ B @ Wb] + bias) [+ R]. W [128(in)][128(out)] row-major.
template <bool DUAL, bool SW, bool RES>
__global__ __launch_bounds__(512, 1) void k_gemmT(
    const float* __restrict__ A, const float* __restrict__ Wa,
    const float* __restrict__ B, const float* __restrict__ Wb,
    const float* __restrict__ bias, const float* __restrict__ R,
    float* __restrict__ out, int n) {
    constexpr int WW = 132;   // float2 row width for W (n-major)
    constexpr int AW2 = 68;   // float2 row width for A chunk (64 cols)
    extern __shared__ float sh[];
    float2* Ws  = (float2*)sh;                 // [128][WW]
    float2* As2 = (float2*)sh + 128 * WW;      // [128][AW2]
    int tid = threadIdx.x, w = tid >> 5, lane = tid & 31, g = lane >> 2, t = lane & 3;
    int wg = w >> 3, wn = w & 7;
    int r0 = blockIdx.x * 128;

    float acc[4][2][4];
    #pragma unroll
    for (int mf = 0; mf < 4; mf++)
        #pragma unroll
        for (int nf = 0; nf < 2; nf++)
            #pragma unroll
            for (int i = 0; i < 4; i++) acc[mf][nf][i] = 0.f;

    const int NPASS = DUAL ? 2 : 1;
    for (int p = 0; p < NPASS; p++) {
        const float* Ain = p ? B : A;
        const float* Win = p ? Wb : Wa;
        __syncthreads();
        for (int i = tid; i < 128 * 128; i += 512) {
            int k = i >> 7, nn = i & 127;
            Ws[nn * WW + k] = split2(Win[i]);
        }
        for (int c = 0; c < 2; c++) {
            __syncthreads();
            for (int i = tid; i < 128 * 64; i += 512) {
                int r = i >> 6, kl = i & 63;
                int row = r0 + r;
                float v = (row < n) ? Ain[(size_t)row * 128 + c * 64 + kl] : 0.f;
                As2[r * AW2 + kl] = split2(v);
            }
            __syncthreads();
            #pragma unroll
            for (int ks = 0; ks < 8; ks++) {
                int kl = ks * 8;
                int kg = c * 64 + kl;
                uint32_t bh[2][2], bl[2][2];
                #pragma unroll
                for (int nf = 0; nf < 2; nf++) {
                    int nn = 16 * wn + 8 * nf + g;
                    float2 b0 = Ws[nn * WW + kg + t];
                    float2 b1 = Ws[nn * WW + kg + t + 4];
                    bh[nf][0] = __float_as_uint(b0.x); bl[nf][0] = __float_as_uint(b0.y);
                    bh[nf][1] = __float_as_uint(b1.x); bl[nf][1] = __float_as_uint(b1.y);
                }
                #pragma unroll
                for (int mf = 0; mf < 4; mf++) {
                    int r = wg * 64 + mf * 16 + g;
                    float2 a0 = As2[r * AW2 + kl + t];
                    float2 a1 = As2[(r + 8) * AW2 + kl + t];
                    float2 a2 = As2[r * AW2 + kl + t + 4];
                    float2 a3 = As2[(r + 8) * AW2 + kl + t + 4];
                    #pragma unroll
                    for (int nf = 0; nf < 2; nf++)
                        mma3(acc[mf][nf], a0, a1, a2, a3,
                             bh[nf][0], bh[nf][1], bl[nf][0], bl[nf][1]);
                }
            }
        }
    }
    float2 bb[2];
    #pragma unroll
    for (int nf = 0; nf < 2; nf++) bb[nf] = *(const float2*)&bias[16 * wn + 8 * nf + 2 * t];
    #pragma unroll
    for (int mf = 0; mf < 4; mf++) {
        #pragma unroll
        for (int half = 0; half < 2; half++) {
            int row = r0 + wg * 64 + mf * 16 + g + 8 * half;
            if (row < n) {
                #pragma unroll
                for (int nf = 0; nf < 2; nf++) {
                    int col = 16 * wn + 8 * nf + 2 * t;
                    float vx = acc[mf][nf][2 * half + 0] + bb[nf].x;
                    float vy = acc[mf][nf][2 * half + 1] + bb[nf].y;
                    if (SW) { vx = vx / (1.f + expf(-vx)); vy = vy / (1.f + expf(-vy)); }
                    if (RES) {
                        float2 rv = *(const float2*)&R[(size_t)row * 128 + col];
                        vx += rv.x; vy += rv.y;
                    }
                    *(float2*)&out[(size_t)row * 128 + col] = make_float2(vx, vy);
                }
            }
        }
    }
}

// ---------------- tensor-core edge GEMM + gather/scatter (512 threads) ----------------
template <int F>
__global__ __launch_bounds__(512, 1) void k_edgeT(
    const float* __restrict__ feat, const float* __restrict__ bhi,
    const float* __restrict__ blo, const int* __restrict__ ei,
    const float* __restrict__ xh, float* __restrict__ agg, int E) {
    constexpr int KTOT = (F == 147) ? 152 : 24;
    constexpr int CS = (F == 147) ? 40 : 24;
    constexpr int NCH = (KTOT + CS - 1) / CS;
    constexpr int AW2 = CS + 4;    // 44 / 28 (float2 width)
    constexpr int BW = KTOT + 4;   // 156 / 28 (float2 width)
    extern __shared__ float sh[];
    float2* Bs  = (float2*)sh;                     // [128][BW]
    float2* As2 = (float2*)sh + 128 * BW;          // [128][AW2]
    // epilogue staging: for F==147 overlay on As2 (33792B <= 45056B); else separate
    float* fs = (F == 147) ? (float*)As2 : (float*)((float2*)As2 + 128 * AW2);
    float* send = (F == 147) ? (float*)((float2*)As2 + 128 * AW2) : (fs + 64 * 132);
    int* srcs = (int*)send;
    int* dsts = srcs + 128;

    int tid = threadIdx.x, w = tid >> 5, lane = tid & 31, g = lane >> 2, t = lane & 3;
    int wg = w >> 3, wn = w & 7;

    // stage split weights (single pass, zero-padded)
    for (int i = tid; i < 128 * BW; i += 512) {
        int nn = i / BW, k = i % BW;
        Bs[i] = (k < F) ? make_float2(bhi[nn * F + k], blo[nn * F + k])
                        : make_float2(0.f, 0.f);
    }

    int ntiles = (E + 127) >> 7;
    for (int tile = blockIdx.x; tile < ntiles; tile += gridDim.x) {
        float acc[4][2][4];
        #pragma unroll
        for (int mf = 0; mf < 4; mf++)
            #pragma unroll
            for (int nf = 0; nf < 2; nf++)
                #pragma unroll
                for (int i = 0; i < 4; i++) acc[mf][nf][i] = 0.f;

        if (tid < 128) {
            int ed = tile * 128 + tid;
            srcs[tid] = (ed < E) ? ei[ed] : 0;
            dsts[tid] = (ed < E) ? ei[(size_t)E + ed] : 0;
        }
        for (int c = 0; c < NCH; c++) {
            int koff = c * CS;
            int cs = (KTOT - koff < CS) ? (KTOT - koff) : CS;
            __syncthreads();
            for (int i = tid; i < 128 * cs; i += 512) {
                int r = i / cs, kl = i % cs;
                int k = koff + kl;
                int ed = tile * 128 + r;
                float v = (ed < E && k < F) ? feat[(size_t)ed * F + k] : 0.f;
                As2[r * AW2 + kl] = split2(v);
            }
            __syncthreads();
            for (int ks = 0; ks < cs / 8; ks++) {
                int kl = ks * 8;
                int kg = koff + kl;
                uint32_t bh[2][2], bl[2][2];
                #pragma unroll
                for (int nf = 0; nf < 2; nf++) {
                    int nn = 16 * wn + 8 * nf + g;
                    float2 b0 = Bs[nn * BW + kg + t];
                    float2 b1 = Bs[nn * BW + kg + t + 4];
                    bh[nf][0] = __float_as_uint(b0.x); bl[nf][0] = __float_as_uint(b0.y);
                    bh[nf][1] = __float_as_uint(b1.x); bl[nf][1] = __float_as_uint(b1.y);
                }
                #pragma unroll
                for (int mf = 0; mf < 4; mf++) {
                    int r = wg * 64 + mf * 16 + g;
                    float2 a0 = As2[r * AW2 + kl + t];
                    float2 a1 = As2[(r + 8) * AW2 + kl + t];
                    float2 a2 = As2[r * AW2 + kl + t + 4];
                    float2 a3 = As2[(r + 8) * AW2 + kl + t + 4];
                    #pragma unroll
                    for (int nf = 0; nf < 2; nf++)
                        mma3(acc[mf][nf], a0, a1, a2, a3,
                             bh[nf][0], bh[nf][1], bl[nf][0], bl[nf][1]);
                }
            }
        }
        // epilogue: per 64-row half, stage f, vector-atomic scatter
        #pragma unroll
        for (int h = 0; h < 2; h++) {
            __syncthreads();
            if (wg == h) {
                #pragma unroll
                for (int mf = 0; mf < 4; mf++) {
                    int rb = mf * 16 + g;
                    #pragma unroll
                    for (int nf = 0; nf < 2; nf++) {
                        int col = 16 * wn + 8 * nf + 2 * t;
                        *(float2*)&fs[rb * 132 + col] =
                            make_float2(acc[mf][nf][0], acc[mf][nf][1]);
                        *(float2*)&fs[(rb + 8) * 132 + col] =
                            make_float2(acc[mf][nf][2], acc[mf][nf][3]);
                    }
                }
            }
            __syncthreads();
            int rl = tid >> 3, q = tid & 7;
            int ed = tile * 128 + h * 64 + rl;
            if (ed < E) {
                int s = srcs[h * 64 + rl], d = dsts[h * 64 + rl];
                const float4* xr = (const float4*)(xh + (size_t)s * 128);
                float4* ar = (float4*)(agg + (size_t)d * 128);
                #pragma unroll
                for (int i = 0; i < 4; i++) {
                    int c4 = q + 8 * i;
                    float4 f = *(float4*)&fs[rl * 132 + 4 * c4];
                    float4 xv = xr[c4];
                    atomicAdd(ar + c4,
                              make_float4(f.x * xv.x, f.y * xv.y, f.z * xv.z, f.w * xv.w));
                }
            }
        }
        __syncthreads();
    }
}

// ---------------- GraphNorm pieces ----------------
__global__ void k_gsum(const float* __restrict__ h, const int* __restrict__ batch, int n) {
    int idx = blockIdx.x * blockDim.x + threadIdx.x;
    if (idx >= n * HH) return;
    int i = idx >> 7, c = idx & 127;
    int g = batch[i];
    if (c == 0) atomicAdd(&g_gcnt[g], 1.f);
    atomicAdd(&g_gsum[g * HH + c], h[idx]);
}

__global__ void k_center(const float* __restrict__ h, const int* __restrict__ batch,
                         const float* __restrict__ ms, int n) {
    int idx = blockIdx.x * blockDim.x + threadIdx.x;
    if (idx >= n * HH) return;
    int i = idx >> 7, c = idx & 127;
    int g = batch[i];
    float cnt = g_gcnt[g]; if (cnt < 1.f) cnt = 1.f;
    float mean = g_gsum[g * HH + c] / cnt;
    float o = h[idx] - mean * ms[c];
    g_on[idx] = o;
    atomicAdd(&g_gsq[g * HH + c], o * o);
}

__global__ void k_norm(const int* __restrict__ batch,
                       const float* __restrict__ w, const float* __restrict__ b, int n) {
    int idx = blockIdx.x * blockDim.x + threadIdx.x;
    if (idx >= n * HH) return;
    int i = idx >> 7, c = idx & 127;
    int g = batch[i];
    float cnt = g_gcnt[g]; if (cnt < 1.f) cnt = 1.f;
    float var = g_gsq[g * HH + c] / cnt;
    g_on[idx] = w[c] * g_on[idx] * rsqrtf(var + 1e-5f) + b[c];
}

// ---------------- launch ----------------
extern "C" void kernel_launch(void* const* d_in, const int* in_sizes, int n_in,
                              void* d_out, int out_size) {
    const float* x          = (const float*)d_in[0];
    const float* feature1   = (const float*)d_in[1];
    const float* feature2   = (const float*)d_in[2];
    const int*   edge_index = (const int*)d_in[3];
    const int*   batch      = (const int*)d_in[4];
    const float* lin_w        = (const float*)d_in[5];
    const float* lin_b        = (const float*)d_in[6];
    const float* f1_w1        = (const float*)d_in[7];
    const float* f1_w2        = (const float*)d_in[8];
    const float* f2_w1        = (const float*)d_in[9];
    const float* f2_w2        = (const float*)d_in[10];
    const float* conv1_rel_w  = (const float*)d_in[11];
    const float* conv1_rel_b  = (const float*)d_in[12];
    const float* conv1_root_w = (const float*)d_in[13];
    const float* conv2_rel_w  = (const float*)d_in[14];
    const float* conv2_rel_b  = (const float*)d_in[15];
    const float* conv2_root_w = (const float*)d_in[16];
    const float* lin1_w       = (const float*)d_in[17];
    const float* lin1_b       = (const float*)d_in[18];
    const float* lin2_w       = (const float*)d_in[19];
    const float* lin2_b       = (const float*)d_in[20];
    const float* lincat_w     = (const float*)d_in[21];
    const float* lincat_b     = (const float*)d_in[22];
    const float* norm_w       = (const float*)d_in[23];
    const float* norm_b       = (const float*)d_in[24];
    const float* norm_ms      = (const float*)d_in[25];
    const float* lins_w       = (const float*)d_in[26];
    const float* lins_b       = (const float*)d_in[27];
    const float* final_w      = (const float*)d_in[28];
    const float* final_b      = (const float*)d_in[29];

    int N_ = in_sizes[0] / HH;
    int E_ = in_sizes[3] / 2;

    static float *p_xh = nullptr, *p_agg1, *p_agg2, *p_c, *p_ha, *p_hb, *p_on;
    static float *p_wa_hi, *p_wa_lo, *p_wb_hi, *p_wb_lo;
    if (!p_xh) {
        cudaGetSymbolAddress((void**)&p_xh,   g_xh);
        cudaGetSymbolAddress((void**)&p_agg1, g_agg1);
        cudaGetSymbolAddress((void**)&p_agg2, g_agg2);
        cudaGetSymbolAddress((void**)&p_c,    g_c);
        cudaGetSymbolAddress((void**)&p_ha,   g_ha);
        cudaGetSymbolAddress((void**)&p_hb,   g_hb);
        cudaGetSymbolAddress((void**)&p_on,   g_on);
        cudaGetSymbolAddress((void**)&p_wa_hi, g_w12a_hi);
        cudaGetSymbolAddress((void**)&p_wa_lo, g_w12a_lo);
        cudaGetSymbolAddress((void**)&p_wb_hi, g_w12b_hi);
        cudaGetSymbolAddress((void**)&p_wb_lo, g_w12b_lo);
    }

    const int sme1 = (128 * 156 + 128 * 44) * 8 + 1024;            // ~205.8 KB
    const int sme2 = (128 * 28 + 128 * 28) * 8 + 64 * 132 * 4 + 1024;  // ~92 KB
    const int smg  = (128 * 132 + 128 * 68) * 8 + 256;             // ~205 KB
    static bool attr_done = false;
    if (!attr_done) {
        cudaFuncSetAttribute(k_edgeT<147>, cudaFuncAttributeMaxDynamicSharedMemorySize, sme1);
        cudaFuncSetAttribute(k_edgeT<21>,  cudaFuncAttributeMaxDynamicSharedMemorySize, sme2);
        cudaFuncSetAttribute(k_gemmT<false, true, false>,  cudaFuncAttributeMaxDynamicSharedMemorySize, smg);
        cudaFuncSetAttribute(k_gemmT<true, false, false>,  cudaFuncAttributeMaxDynamicSharedMemorySize, smg);
        cudaFuncSetAttribute(k_gemmT<true, false, true>,   cudaFuncAttributeMaxDynamicSharedMemorySize, smg);
        cudaFuncSetAttribute(k_gemmT<false, true, true>,   cudaFuncAttributeMaxDynamicSharedMemorySize, smg);
        cudaFuncSetAttribute(k_gemmT<false, false, false>, cudaFuncAttributeMaxDynamicSharedMemorySize, smg);
        attr_done = true;
    }

    int NH_ = N_ * HH;
    int gZ = (NH_ + 255) / 256;
    int gB = (N_ + 127) / 128;

    // launches 0-4: w12 x2, xh gemm, zero x2 (so launch #5 = k_edgeT<147> for ncu -s 5)
    k_w12<147><<<147, 128>>>(f1_w1, f1_w2, p_wa_hi, p_wa_lo);
    k_w12<21><<<21, 128>>>(f2_w1, f2_w2, p_wb_hi, p_wb_lo);
    k_gemmT<false, true, false><<<gB, 512, smg>>>(x, lin_w, nullptr, nullptr, lin_b, nullptr, p_xh, N_);
    k_zero<<<gZ, 256>>>(0, NH_);
    k_zero<<<gZ, 256>>>(1, NH_);

    // edge GEMM + gather + scatter
    k_edgeT<147><<<148, 512, sme1>>>(feature1, p_wa_hi, p_wa_lo, edge_index, p_xh, p_agg1, E_);
    k_edgeT<21><<<296, 512, sme2>>>(feature2, p_wb_hi, p_wb_lo, edge_index, p_xh, p_agg2, E_);

    // conv1 / lin1
    k_gemmT<true, false, false><<<gB, 512, smg>>>(p_agg1, conv1_rel_w, p_xh, conv1_root_w, conv1_rel_b, nullptr, p_c, N_);
    k_gemmT<false, true, false><<<gB, 512, smg>>>(p_c, lin1_w, nullptr, nullptr, lin1_b, nullptr, p_agg1, N_);
    // conv2 / lin2
    k_gemmT<true, false, false><<<gB, 512, smg>>>(p_agg2, conv2_rel_w, p_xh, conv2_root_w, conv2_rel_b, nullptr, p_c, N_);
    k_gemmT<false, true, false><<<gB, 512, smg>>>(p_c, lin2_w, nullptr, nullptr, lin2_b, nullptr, p_agg2, N_);

    // h = cat(h1,h2) @ lincat + b + xh
    k_gemmT<true, false, true><<<gB, 512, smg>>>(p_agg1, lincat_w, p_agg2, lincat_w + HH * HH, lincat_b, p_xh, p_ha, N_);

    // residual lins: h = swish(h@W+b) + h
    k_gemmT<false, true, true><<<gB, 512, smg>>>(p_ha, lins_w,               nullptr, nullptr, lins_b,          p_ha, p_hb, N_);
    k_gemmT<false, true, true><<<gB, 512, smg>>>(p_hb, lins_w + 1 * HH * HH, nullptr, nullptr, lins_b + 1 * HH, p_hb, p_ha, N_);
    k_gemmT<false, true, true><<<gB, 512, smg>>>(p_ha, lins_w + 2 * HH * HH, nullptr, nullptr, lins_b + 2 * HH, p_ha, p_hb, N_);

    // GraphNorm
    k_zero<<<(GG * HH + 255) / 256, 256>>>(2, NH_);
    k_gsum<<<gZ, 256>>>(p_hb, batch, N_);
    k_center<<<gZ, 256>>>(p_hb, batch, norm_ms, N_);
    k_norm<<<gZ, 256>>>(batch, norm_w, norm_b, N_);

    // final projection
    k_gemmT<false, false, false><<<gB, 512, smg>>>(p_on, final_w, nullptr, nullptr, final_b, nullptr, (float*)d_out, N_);
}

// round 5
// speedup vs baseline: 1.4926x; 1.4926x over previous
#include <cuda_runtime.h>
#include <cuda_bf16.h>
#include <cstdint>
#include <math.h>

// ---------------- problem constants ----------------
#define HH 128
#define GG 512
#define MAXN 50000
#define NHH (MAXN * HH)

// ---------------- device scratch ----------------
__device__ float g_xh[NHH];
__device__ float g_agg1[NHH];
__device__ float g_agg2[NHH];
__device__ float g_c[NHH];
__device__ float g_ha[NHH];
__device__ float g_hb[NHH];
__device__ float g_on[NHH];
__device__ float g_gsum[GG * HH];
__device__ float g_gsq[GG * HH];
__device__ float g_gcnt[GG];
__device__ uint2 g_w12a[128 * 84];   // packed split-bf16 W12 for feature1, n-major kpairs
__device__ uint2 g_w12b[128 * 20];   // for feature2

// ---------------- bf16 split helpers ----------------
__device__ __forceinline__ uint2 splitbf2(float x0, float x1) {
    __nv_bfloat16 h0 = __float2bfloat16(x0);
    __nv_bfloat16 h1 = __float2bfloat16(x1);
    float r0 = x0 - __bfloat162float(h0);
    float r1 = x1 - __bfloat162float(h1);
    __nv_bfloat16 l0 = __float2bfloat16(r0);
    __nv_bfloat16 l1 = __float2bfloat16(r1);
    uint32_t hp = (uint32_t)__bfloat16_as_ushort(h0) |
                  ((uint32_t)__bfloat16_as_ushort(h1) << 16);
    uint32_t lp = (uint32_t)__bfloat16_as_ushort(l0) |
                  ((uint32_t)__bfloat16_as_ushort(l1) << 16);
    return make_uint2(hp, lp);
}

__device__ __forceinline__ void mma16(float* d, uint32_t a0, uint32_t a1, uint32_t a2,
                                      uint32_t a3, uint32_t b0, uint32_t b1) {
    asm volatile(
        "mma.sync.aligned.m16n8k16.row.col.f32.bf16.bf16.f32 "
        "{%0,%1,%2,%3}, {%4,%5,%6,%7}, {%8,%9}, {%0,%1,%2,%3};\n"
        : "+f"(d[0]), "+f"(d[1]), "+f"(d[2]), "+f"(d[3])
        : "r"(a0), "r"(a1), "r"(a2), "r"(a3), "r"(b0), "r"(b1));
}

// 3-term split mma: (ah+al)(bh+bl) ~= ah*bh + ah*bl + al*bh
__device__ __forceinline__ void mma3(float* d, const uint2& a0, const uint2& a1,
                                     const uint2& a2, const uint2& a3,
                                     uint32_t bh0, uint32_t bh1, uint32_t bl0, uint32_t bl1) {
    mma16(d, a0.x, a1.x, a2.x, a3.x, bh0, bh1);
    mma16(d, a0.x, a1.x, a2.x, a3.x, bl0, bl1);
    mma16(d, a0.y, a1.y, a2.y, a3.y, bh0, bh1);
}

// ---------------- misc kernels ----------------
__global__ void k_zero(int sel, int n) {
    int i = blockIdx.x * blockDim.x + threadIdx.x;
    if (sel == 0) { if (i < n) g_agg1[i] = 0.f; }
    else if (sel == 1) { if (i < n) g_agg2[i] = 0.f; }
    else {
        if (i < GG * HH) { g_gsum[i] = 0.f; g_gsq[i] = 0.f; }
        if (i < GG) g_gcnt[i] = 0.f;
    }
}

// W12[k][n] = sum_m W1[k][m]*W2[m][n]; packed split-bf16, out[n*WP + kp] = {hi2, lo2}
template <int F, int WP>
__global__ void k_w12pack(const float* __restrict__ W1, const float* __restrict__ W2,
                          uint2* __restrict__ out) {
    int n = blockIdx.x;     // 0..127
    int kp = threadIdx.x;   // 0..WP-1
    if (kp >= WP) return;
    int k0 = 2 * kp, k1 = 2 * kp + 1;
    float a0 = 0.f, a1 = 0.f;
    for (int m = 0; m < 64; m++) {
        float w2 = W2[m * 128 + n];
        if (k0 < F) a0 += W1[k0 * 64 + m] * w2;
        if (k1 < F) a1 += W1[k1 * 64 + m] * w2;
    }
    out[n * WP + kp] = splitbf2(a0, a1);
}

// ---------------- bf16 tensor-core node GEMM (512 threads, m32/n32 per warp) ----------------
// out = [swish](A @ Wa [+ B @ Wb] + bias) [+ R]. W [128(in)][128(out)] row-major.
template <bool DUAL, bool SW, bool RES>
__global__ __launch_bounds__(512, 1) void k_gemmT(
    const float* __restrict__ A, const float* __restrict__ Wa,
    const float* __restrict__ B, const float* __restrict__ Wb,
    const float* __restrict__ bias, const float* __restrict__ R,
    float* __restrict__ out, int n) {
    constexpr int WW = 68;   // uint2 row width (64 kpairs + 4 pad)
    extern __shared__ uint2 shu[];
    uint2* Ws  = shu;              // [128][WW] n-major
    uint2* As2 = shu + 128 * WW;   // [128][WW]
    int tid = threadIdx.x, w = tid >> 5, lane = tid & 31, g = lane >> 2, t = lane & 3;
    int wg = w >> 2, wn = w & 3;   // 4 m-groups x 4 n-groups
    int r0 = blockIdx.x * 128;

    float acc[2][4][4];
    #pragma unroll
    for (int mf = 0; mf < 2; mf++)
        #pragma unroll
        for (int nf = 0; nf < 4; nf++)
            #pragma unroll
            for (int i = 0; i < 4; i++) acc[mf][nf][i] = 0.f;

    const int NPASS = DUAL ? 2 : 1;
    for (int p = 0; p < NPASS; p++) {
        const float* Ain = p ? B : A;
        const float* Win = p ? Wb : Wa;
        __syncthreads();
        // stage W: [n][kp] from row-major [k][n]
        for (int i = tid; i < 128 * 64; i += 512) {
            int nn = i & 127, kp = i >> 7;
            float w0 = Win[(2 * kp) * 128 + nn];
            float w1 = Win[(2 * kp + 1) * 128 + nn];
            Ws[nn * WW + kp] = splitbf2(w0, w1);
        }
        // stage A: [r][kp]
        for (int i = tid; i < 128 * 64; i += 512) {
            int r = i >> 6, kp = i & 63;
            int row = r0 + r;
            float2 v = (row < n) ? *(const float2*)(Ain + (size_t)row * 128 + 2 * kp)
                                 : make_float2(0.f, 0.f);
            As2[r * WW + kp] = splitbf2(v.x, v.y);
        }
        __syncthreads();
        #pragma unroll
        for (int ks = 0; ks < 8; ks++) {
            int kp0 = ks * 8;
            uint32_t bh[4][2], bl[4][2];
            #pragma unroll
            for (int nf = 0; nf < 4; nf++) {
                int nn = wn * 32 + nf * 8 + g;
                uint2 b0 = Ws[nn * WW + kp0 + t];
                uint2 b1 = Ws[nn * WW + kp0 + t + 4];
                bh[nf][0] = b0.x; bl[nf][0] = b0.y;
                bh[nf][1] = b1.x; bl[nf][1] = b1.y;
            }
            #pragma unroll
            for (int mf = 0; mf < 2; mf++) {
                int r = wg * 32 + mf * 16 + g;
                uint2 a0 = As2[r * WW + kp0 + t];
                uint2 a1 = As2[(r + 8) * WW + kp0 + t];
                uint2 a2 = As2[r * WW + kp0 + t + 4];
                uint2 a3 = As2[(r + 8) * WW + kp0 + t + 4];
                #pragma unroll
                for (int nf = 0; nf < 4; nf++)
                    mma3(acc[mf][nf], a0, a1, a2, a3,
                         bh[nf][0], bh[nf][1], bl[nf][0], bl[nf][1]);
            }
        }
    }
    // epilogue
    float2 bb[4];
    #pragma unroll
    for (int nf = 0; nf < 4; nf++) bb[nf] = *(const float2*)&bias[wn * 32 + nf * 8 + 2 * t];
    #pragma unroll
    for (int mf = 0; mf < 2; mf++) {
        #pragma unroll
        for (int half = 0; half < 2; half++) {
            int row = r0 + wg * 32 + mf * 16 + g + 8 * half;
            if (row < n) {
                #pragma unroll
                for (int nf = 0; nf < 4; nf++) {
                    int col = wn * 32 + nf * 8 + 2 * t;
                    float vx = acc[mf][nf][2 * half + 0] + bb[nf].x;
                    float vy = acc[mf][nf][2 * half + 1] + bb[nf].y;
                    if (SW) { vx = vx / (1.f + expf(-vx)); vy = vy / (1.f + expf(-vy)); }
                    if (RES) {
                        float2 rv = *(const float2*)&R[(size_t)row * 128 + col];
                        vx += rv.x; vy += rv.y;
                    }
                    *(float2*)&out[(size_t)row * 128 + col] = make_float2(vx, vy);
                }
            }
        }
    }
}

// ---------------- bf16 tensor-core edge GEMM + gather/scatter ----------------
// f[128x128] = feat_tile[128xF] @ W12[Fx128]; agg[dst] += f ⊙ xh[src]
// WP: kpair width incl pad; KS16: number of k16 steps
template <int F, int WP, int KS16, bool OVERLAY>
__global__ __launch_bounds__(512, 1) void k_edgeT(
    const float* __restrict__ feat, const uint2* __restrict__ wpk,
    const int* __restrict__ ei, const float* __restrict__ xh,
    float* __restrict__ agg, int E) {
    extern __shared__ uint2 shu[];
    uint2* Bs  = shu;              // [128][WP]
    uint2* As2 = shu + 128 * WP;   // [128][WP]
    float* fs = OVERLAY ? (float*)As2 : (float*)(As2 + 128 * WP);  // [64][132]
    int* srcs = OVERLAY ? (int*)(As2 + 128 * WP) : (int*)(fs + 64 * 132);
    int* dsts = srcs + 128;

    int tid = threadIdx.x, w = tid >> 5, lane = tid & 31, g = lane >> 2, t = lane & 3;
    int wg = w >> 2, wn = w & 3;

    // stage packed weights once
    for (int i = tid; i < 128 * WP; i += 512) Bs[i] = wpk[i];

    int ntiles = (E + 127) >> 7;
    for (int tile = blockIdx.x; tile < ntiles; tile += gridDim.x) {
        float acc[2][4][4];
        #pragma unroll
        for (int mf = 0; mf < 2; mf++)
            #pragma unroll
            for (int nf = 0; nf < 4; nf++)
                #pragma unroll
                for (int i = 0; i < 4; i++) acc[mf][nf][i] = 0.f;

        __syncthreads();
        if (tid < 128) {
            int ed = tile * 128 + tid;
            srcs[tid] = (ed < E) ? ei[ed] : 0;
            dsts[tid] = (ed < E) ? ei[(size_t)E + ed] : 0;
        }
        // stage features split-bf16
        for (int i = tid; i < 128 * WP; i += 512) {
            int r = i / WP, kp = i % WP;
            int ed = tile * 128 + r;
            int k0 = 2 * kp, k1 = 2 * kp + 1;
            float v0 = 0.f, v1 = 0.f;
            if (ed < E) {
                const float* fr = feat + (size_t)ed * F;
                if (k0 < F) v0 = fr[k0];
                if (k1 < F) v1 = fr[k1];
            }
            As2[r * WP + kp] = splitbf2(v0, v1);
        }
        __syncthreads();
        #pragma unroll
        for (int ks = 0; ks < KS16; ks++) {
            int kp0 = ks * 8;
            uint32_t bh[4][2], bl[4][2];
            #pragma unroll
            for (int nf = 0; nf < 4; nf++) {
                int nn = wn * 32 + nf * 8 + g;
                uint2 b0 = Bs[nn * WP + kp0 + t];
                uint2 b1 = Bs[nn * WP + kp0 + t + 4];
                bh[nf][0] = b0.x; bl[nf][0] = b0.y;
                bh[nf][1] = b1.x; bl[nf][1] = b1.y;
            }
            #pragma unroll
            for (int mf = 0; mf < 2; mf++) {
                int r = wg * 32 + mf * 16 + g;
                uint2 a0 = As2[r * WP + kp0 + t];
                uint2 a1 = As2[(r + 8) * WP + kp0 + t];
                uint2 a2 = As2[r * WP + kp0 + t + 4];
                uint2 a3 = As2[(r + 8) * WP + kp0 + t + 4];
                #pragma unroll
                for (int nf = 0; nf < 4; nf++)
                    mma3(acc[mf][nf], a0, a1, a2, a3,
                         bh[nf][0], bh[nf][1], bl[nf][0], bl[nf][1]);
            }
        }
        // epilogue: per 64-row half stage f, then gather xh / vector-atomic scatter
        #pragma unroll
        for (int h = 0; h < 2; h++) {
            __syncthreads();
            if ((wg >> 1) == h) {
                int rbase = (wg & 1) * 32;
                #pragma unroll
                for (int mf = 0; mf < 2; mf++) {
                    int rb = rbase + mf * 16 + g;
                    #pragma unroll
                    for (int nf = 0; nf < 4; nf++) {
                        int col = wn * 32 + nf * 8 + 2 * t;
                        *(float2*)&fs[rb * 132 + col] =
                            make_float2(acc[mf][nf][0], acc[mf][nf][1]);
                        *(float2*)&fs[(rb + 8) * 132 + col] =
                            make_float2(acc[mf][nf][2], acc[mf][nf][3]);
                    }
                }
            }
            __syncthreads();
            int rl = tid >> 3, q = tid & 7;
            int ed = tile * 128 + h * 64 + rl;
            if (ed < E) {
                int s = srcs[h * 64 + rl], d = dsts[h * 64 + rl];
                const float4* xr = (const float4*)(xh + (size_t)s * 128);
                float4* ar = (float4*)(agg + (size_t)d * 128);
                #pragma unroll
                for (int i = 0; i < 4; i++) {
                    int c4 = q + 8 * i;
                    float4 f = *(float4*)&fs[rl * 132 + 4 * c4];
                    float4 xv = xr[c4];
                    atomicAdd(ar + c4,
                              make_float4(f.x * xv.x, f.y * xv.y, f.z * xv.z, f.w * xv.w));
                }
            }
        }
    }
}

// ---------------- GraphNorm pieces ----------------
__global__ void k_gsum(const float* __restrict__ h, const int* __restrict__ batch, int n) {
    int idx = blockIdx.x * blockDim.x + threadIdx.x;
    if (idx >= n * HH) return;
    int i = idx >> 7, c = idx & 127;
    int g = batch[i];
    if (c == 0) atomicAdd(&g_gcnt[g], 1.f);
    atomicAdd(&g_gsum[g * HH + c], h[idx]);
}

__global__ void k_center(const float* __restrict__ h, const int* __restrict__ batch,
                         const float* __restrict__ ms, int n) {
    int idx = blockIdx.x * blockDim.x + threadIdx.x;
    if (idx >= n * HH) return;
    int i = idx >> 7, c = idx & 127;
    int g = batch[i];
    float cnt = g_gcnt[g]; if (cnt < 1.f) cnt = 1.f;
    float mean = g_gsum[g * HH + c] / cnt;
    float o = h[idx] - mean * ms[c];
    g_on[idx] = o;
    atomicAdd(&g_gsq[g * HH + c], o * o);
}

__global__ void k_norm(const int* __restrict__ batch,
                       const float* __restrict__ w, const float* __restrict__ b, int n) {
    int idx = blockIdx.x * blockDim.x + threadIdx.x;
    if (idx >= n * HH) return;
    int i = idx >> 7, c = idx & 127;
    int g = batch[i];
    float cnt = g_gcnt[g]; if (cnt < 1.f) cnt = 1.f;
    float var = g_gsq[g * HH + c] / cnt;
    g_on[idx] = w[c] * g_on[idx] * rsqrtf(var + 1e-5f) + b[c];
}

// ---------------- launch ----------------
extern "C" void kernel_launch(void* const* d_in, const int* in_sizes, int n_in,
                              void* d_out, int out_size) {
    const float* x          = (const float*)d_in[0];
    const float* feature1   = (const float*)d_in[1];
    const float* feature2   = (const float*)d_in[2];
    const int*   edge_index = (const int*)d_in[3];
    const int*   batch      = (const int*)d_in[4];
    const float* lin_w        = (const float*)d_in[5];
    const float* lin_b        = (const float*)d_in[6];
    const float* f1_w1        = (const float*)d_in[7];
    const float* f1_w2        = (const float*)d_in[8];
    const float* f2_w1        = (const float*)d_in[9];
    const float* f2_w2        = (const float*)d_in[10];
    const float* conv1_rel_w  = (const float*)d_in[11];
    const float* conv1_rel_b  = (const float*)d_in[12];
    const float* conv1_root_w = (const float*)d_in[13];
    const float* conv2_rel_w  = (const float*)d_in[14];
    const float* conv2_rel_b  = (const float*)d_in[15];
    const float* conv2_root_w = (const float*)d_in[16];
    const float* lin1_w       = (const float*)d_in[17];
    const float* lin1_b       = (const float*)d_in[18];
    const float* lin2_w       = (const float*)d_in[19];
    const float* lin2_b       = (const float*)d_in[20];
    const float* lincat_w     = (const float*)d_in[21];
    const float* lincat_b     = (const float*)d_in[22];
    const float* norm_w       = (const float*)d_in[23];
    const float* norm_b       = (const float*)d_in[24];
    const float* norm_ms      = (const float*)d_in[25];
    const float* lins_w       = (const float*)d_in[26];
    const float* lins_b       = (const float*)d_in[27];
    const float* final_w      = (const float*)d_in[28];
    const float* final_b      = (const float*)d_in[29];

    int N_ = in_sizes[0] / HH;
    int E_ = in_sizes[3] / 2;

    static float *p_xh = nullptr, *p_agg1, *p_agg2, *p_c, *p_ha, *p_hb, *p_on;
    static uint2 *p_wa, *p_wb;
    if (!p_xh) {
        cudaGetSymbolAddress((void**)&p_xh,   g_xh);
        cudaGetSymbolAddress((void**)&p_agg1, g_agg1);
        cudaGetSymbolAddress((void**)&p_agg2, g_agg2);
        cudaGetSymbolAddress((void**)&p_c,    g_c);
        cudaGetSymbolAddress((void**)&p_ha,   g_ha);
        cudaGetSymbolAddress((void**)&p_hb,   g_hb);
        cudaGetSymbolAddress((void**)&p_on,   g_on);
        cudaGetSymbolAddress((void**)&p_wa,   g_w12a);
        cudaGetSymbolAddress((void**)&p_wb,   g_w12b);
    }

    const int sme1 = 128 * 84 * 8 * 2 + 1024;                // 173,056 B
    const int sme2 = 128 * 20 * 8 * 2 + 64 * 132 * 4 + 1024; // 75,776 B
    const int smg  = 128 * 68 * 8 * 2 + 256;                 // 139,520 B
    static bool attr_done = false;
    if (!attr_done) {
        cudaFuncSetAttribute(k_edgeT<147, 84, 10, true>, cudaFuncAttributeMaxDynamicSharedMemorySize, sme1);
        cudaFuncSetAttribute(k_edgeT<21, 20, 2, false>,  cudaFuncAttributeMaxDynamicSharedMemorySize, sme2);
        cudaFuncSetAttribute(k_gemmT<false, true, false>,  cudaFuncAttributeMaxDynamicSharedMemorySize, smg);
        cudaFuncSetAttribute(k_gemmT<true, false, false>,  cudaFuncAttributeMaxDynamicSharedMemorySize, smg);
        cudaFuncSetAttribute(k_gemmT<true, false, true>,   cudaFuncAttributeMaxDynamicSharedMemorySize, smg);
        cudaFuncSetAttribute(k_gemmT<false, true, true>,   cudaFuncAttributeMaxDynamicSharedMemorySize, smg);
        cudaFuncSetAttribute(k_gemmT<false, false, false>, cudaFuncAttributeMaxDynamicSharedMemorySize, smg);
        attr_done = true;
    }

    int NH_ = N_ * HH;
    int gZ = (NH_ + 255) / 256;
    int gB = (N_ + 127) / 128;

    // launch order chosen so index 3 (the ncu-captured launch) = k_edgeT<147>
    k_w12pack<147, 84><<<128, 84>>>(f1_w1, f1_w2, p_wa);                                  // 0
    k_zero<<<gZ, 256>>>(0, NH_);                                                          // 1
    k_gemmT<false, true, false><<<gB, 512, smg>>>(x, lin_w, nullptr, nullptr, lin_b, nullptr, p_xh, N_);  // 2
    k_edgeT<147, 84, 10, true><<<148, 512, sme1>>>(feature1, p_wa, edge_index, p_xh, p_agg1, E_);         // 3
    k_w12pack<21, 20><<<128, 20>>>(f2_w1, f2_w2, p_wb);                                   // 4
    k_zero<<<gZ, 256>>>(1, NH_);                                                          // 5
    k_edgeT<21, 20, 2, false><<<296, 512, sme2>>>(feature2, p_wb, edge_index, p_xh, p_agg2, E_);          // 6

    // conv1 / lin1
    k_gemmT<true, false, false><<<gB, 512, smg>>>(p_agg1, conv1_rel_w, p_xh, conv1_root_w, conv1_rel_b, nullptr, p_c, N_);
    k_gemmT<false, true, false><<<gB, 512, smg>>>(p_c, lin1_w, nullptr, nullptr, lin1_b, nullptr, p_agg1, N_);
    // conv2 / lin2
    k_gemmT<true, false, false><<<gB, 512, smg>>>(p_agg2, conv2_rel_w, p_xh, conv2_root_w, conv2_rel_b, nullptr, p_c, N_);
    k_gemmT<false, true, false><<<gB, 512, smg>>>(p_c, lin2_w, nullptr, nullptr, lin2_b, nullptr, p_agg2, N_);

    // h = cat(h1,h2) @ lincat + b + xh
    k_gemmT<true, false, true><<<gB, 512, smg>>>(p_agg1, lincat_w, p_agg2, lincat_w + HH * HH, lincat_b, p_xh, p_ha, N_);

    // residual lins: h = swish(h@W+b) + h
    k_gemmT<false, true, true><<<gB, 512, smg>>>(p_ha, lins_w,               nullptr, nullptr, lins_b,          p_ha, p_hb, N_);
    k_gemmT<false, true, true><<<gB, 512, smg>>>(p_hb, lins_w + 1 * HH * HH, nullptr, nullptr, lins_b + 1 * HH, p_hb, p_ha, N_);
    k_gemmT<false, true, true><<<gB, 512, smg>>>(p_ha, lins_w + 2 * HH * HH, nullptr, nullptr, lins_b + 2 * HH, p_ha, p_hb, N_);

    // GraphNorm
    k_zero<<<(GG * HH + 255) / 256, 256>>>(2, NH_);
    k_gsum<<<gZ, 256>>>(p_hb, batch, N_);
    k_center<<<gZ, 256>>>(p_hb, batch, norm_ms, N_);
    k_norm<<<gZ, 256>>>(batch, norm_w, norm_b, N_);

    // final projection
    k_gemmT<false, false, false><<<gB, 512, smg>>>(p_on, final_w, nullptr, nullptr, final_b, nullptr, (float*)d_out, N_);
}

// round 8
// speedup vs baseline: 1.6303x; 1.0922x over previous
#include <cuda_runtime.h>
#include <cuda_bf16.h>
#include <cstdint>
#include <math.h>

// ---------------- problem constants ----------------
#define HH 128
#define GG 512
#define MAXN 50000
#define NHH (MAXN * HH)

// ---------------- device scratch ----------------
__device__ float g_xh[NHH];
__device__ float g_agg1[NHH];
__device__ float g_agg2[NHH];
__device__ float g_c[NHH];
__device__ float g_ha[NHH];
__device__ float g_hb[NHH];
__device__ float g_on[NHH];
__device__ float g_gsum[GG * HH];
__device__ float g_gsq[GG * HH];
__device__ float g_gcnt[GG];
__device__ uint2 g_w12a[128 * 84];   // packed split-bf16 W12 (feature1), n-major kpairs
__device__ uint2 g_w12b[128 * 20];   // (feature2)

// ---------------- bf16 split helpers ----------------
__device__ __forceinline__ uint2 splitbf2p(float2 v) {
    __nv_bfloat162 h = __float22bfloat162_rn(v);
    float2 hv = __bfloat1622float2(h);
    __nv_bfloat162 l = __float22bfloat162_rn(make_float2(v.x - hv.x, v.y - hv.y));
    uint2 r;
    r.x = *reinterpret_cast<uint32_t*>(&h);
    r.y = *reinterpret_cast<uint32_t*>(&l);
    return r;
}

__device__ __forceinline__ void mma16(float* d, uint32_t a0, uint32_t a1, uint32_t a2,
                                      uint32_t a3, uint32_t b0, uint32_t b1) {
    asm volatile(
        "mma.sync.aligned.m16n8k16.row.col.f32.bf16.bf16.f32 "
        "{%0,%1,%2,%3}, {%4,%5,%6,%7}, {%8,%9}, {%0,%1,%2,%3};\n"
        : "+f"(d[0]), "+f"(d[1]), "+f"(d[2]), "+f"(d[3])
        : "r"(a0), "r"(a1), "r"(a2), "r"(a3), "r"(b0), "r"(b1));
}

// 3-term split mma: (ah+al)(bh+bl) ~= ah*bh + ah*bl + al*bh
__device__ __forceinline__ void mma3(float* d, const uint2& a0, const uint2& a1,
                                     const uint2& a2, const uint2& a3,
                                     uint32_t bh0, uint32_t bh1, uint32_t bl0, uint32_t bl1) {
    mma16(d, a0.x, a1.x, a2.x, a3.x, bh0, bh1);
    mma16(d, a0.x, a1.x, a2.x, a3.x, bl0, bl1);
    mma16(d, a0.y, a1.y, a2.y, a3.y, bh0, bh1);
}

// ---------------- misc kernels ----------------
__global__ void k_zero(int sel, int n) {
    int i = blockIdx.x * blockDim.x + threadIdx.x;
    if (sel == 0) { if (i < n) g_agg1[i] = 0.f; }
    else if (sel == 1) { if (i < n) g_agg2[i] = 0.f; }
    else {
        if (i < GG * HH) { g_gsum[i] = 0.f; g_gsq[i] = 0.f; }
        if (i < GG) g_gcnt[i] = 0.f;
    }
}

// W12[k][n] = sum_m W1[k][m]*W2[m][n]; packed split-bf16, out[n*WP + kp]
template <int F, int WP>
__global__ void k_w12pack(const float* __restrict__ W1, const float* __restrict__ W2,
                          uint2* __restrict__ out) {
    int n = blockIdx.x;
    int kp = threadIdx.x;
    if (kp >= WP) return;
    int k0 = 2 * kp, k1 = 2 * kp + 1;
    float a0 = 0.f, a1 = 0.f;
    for (int m = 0; m < 64; m++) {
        float w2 = W2[m * 128 + n];
        if (k0 < F) a0 += W1[k0 * 64 + m] * w2;
        if (k1 < F) a1 += W1[k1 * 64 + m] * w2;
    }
    out[n * WP + kp] = splitbf2p(make_float2(a0, a1));
}

// ---------------- bf16 tensor-core node GEMM (512 threads, m32/n32 per warp) ----------------
template <bool DUAL, bool SW, bool RES>
__global__ __launch_bounds__(512, 1) void k_gemmT(
    const float* __restrict__ A, const float* __restrict__ Wa,
    const float* __restrict__ B, const float* __restrict__ Wb,
    const float* __restrict__ bias, const float* __restrict__ R,
    float* __restrict__ out, int n) {
    constexpr int WW = 68;
    extern __shared__ uint2 shu[];
    uint2* Ws  = shu;
    uint2* As2 = shu + 128 * WW;
    int tid = threadIdx.x, w = tid >> 5, lane = tid & 31, g = lane >> 2, t = lane & 3;
    int wg = w >> 2, wn = w & 3;
    int r0 = blockIdx.x * 128;

    float acc[2][4][4];
    #pragma unroll
    for (int mf = 0; mf < 2; mf++)
        #pragma unroll
        for (int nf = 0; nf < 4; nf++)
            #pragma unroll
            for (int i = 0; i < 4; i++) acc[mf][nf][i] = 0.f;

    const int NPASS = DUAL ? 2 : 1;
    for (int p = 0; p < NPASS; p++) {
        const float* Ain = p ? B : A;
        const float* Win = p ? Wb : Wa;
        __syncthreads();
        for (int i = tid; i < 128 * 64; i += 512) {
            int nn = i & 127, kp = i >> 7;
            float w0 = Win[(2 * kp) * 128 + nn];
            float w1 = Win[(2 * kp + 1) * 128 + nn];
            Ws[nn * WW + kp] = splitbf2p(make_float2(w0, w1));
        }
        for (int i = tid; i < 128 * 64; i += 512) {
            int r = i >> 6, kp = i & 63;
            int row = r0 + r;
            float2 v = (row < n) ? *(const float2*)(Ain + (size_t)row * 128 + 2 * kp)
                                 : make_float2(0.f, 0.f);
            As2[r * WW + kp] = splitbf2p(v);
        }
        __syncthreads();
        #pragma unroll
        for (int ks = 0; ks < 8; ks++) {
            int kp0 = ks * 8;
            uint32_t bh[4][2], bl[4][2];
            #pragma unroll
            for (int nf = 0; nf < 4; nf++) {
                int nn = wn * 32 + nf * 8 + g;
                uint2 b0 = Ws[nn * WW + kp0 + t];
                uint2 b1 = Ws[nn * WW + kp0 + t + 4];
                bh[nf][0] = b0.x; bl[nf][0] = b0.y;
                bh[nf][1] = b1.x; bl[nf][1] = b1.y;
            }
            #pragma unroll
            for (int mf = 0; mf < 2; mf++) {
                int r = wg * 32 + mf * 16 + g;
                uint2 a0 = As2[r * WW + kp0 + t];
                uint2 a1 = As2[(r + 8) * WW + kp0 + t];
                uint2 a2 = As2[r * WW + kp0 + t + 4];
                uint2 a3 = As2[(r + 8) * WW + kp0 + t + 4];
                #pragma unroll
                for (int nf = 0; nf < 4; nf++)
                    mma3(acc[mf][nf], a0, a1, a2, a3,
                         bh[nf][0], bh[nf][1], bl[nf][0], bl[nf][1]);
            }
        }
    }
    float2 bb[4];
    #pragma unroll
    for (int nf = 0; nf < 4; nf++) bb[nf] = *(const float2*)&bias[wn * 32 + nf * 8 + 2 * t];
    #pragma unroll
    for (int mf = 0; mf < 2; mf++) {
        #pragma unroll
        for (int half = 0; half < 2; half++) {
            int row = r0 + wg * 32 + mf * 16 + g + 8 * half;
            if (row < n) {
                #pragma unroll
                for (int nf = 0; nf < 4; nf++) {
                    int col = wn * 32 + nf * 8 + 2 * t;
                    float vx = acc[mf][nf][2 * half + 0] + bb[nf].x;
                    float vy = acc[mf][nf][2 * half + 1] + bb[nf].y;
                    if (SW) { vx = vx / (1.f + expf(-vx)); vy = vy / (1.f + expf(-vy)); }
                    if (RES) {
                        float2 rv = *(const float2*)&R[(size_t)row * 128 + col];
                        vx += rv.x; vy += rv.y;
                    }
                    *(float2*)&out[(size_t)row * 128 + col] = make_float2(vx, vy);
                }
            }
        }
    }
}

// ---------------- pipelined edge GEMM (F=147), 512 threads ----------------
// K=160 (padded), 2 chunks x 80k (40 kpairs), double-buffered A staging.
__global__ __launch_bounds__(512, 1) void k_edgeP(
    const float* __restrict__ feat, const uint2* __restrict__ wpk,
    const int* __restrict__ ei, const float* __restrict__ xh,
    float* __restrict__ agg, int E) {
    constexpr int F = 147;
    constexpr int WP = 84;   // B kpair width (80 + 4 pad)
    constexpr int CS = 40;   // chunk kpairs
    constexpr int AW = 44;   // A chunk buf width
    extern __shared__ uint2 shu[];
    uint2* Bs = shu;                       // [128][84]
    uint2* Ab[2] = { shu + 128 * WP, shu + 128 * WP + 128 * AW };  // [128][44] x2
    float* fs = (float*)(shu + 128 * WP + 2 * 128 * AW);           // [64][132]
    int* srcs = (int*)(fs + 64 * 132);
    int* dsts = srcs + 128;

    int tid = threadIdx.x, w = tid >> 5, lane = tid & 31, g = lane >> 2, t = lane & 3;
    int wg = w >> 2, wn = w & 3;

    for (int i = tid; i < 128 * WP; i += 512) Bs[i] = wpk[i];

    auto stage = [&](int tile, int c, uint2* buf) {
        int base = tile * 128;
        for (int i = tid; i < 128 * CS; i += 512) {
            int r = i / CS, kpl = i - r * CS;
            int k0 = 2 * (c * CS + kpl);
            int ed = base + r;
            float v0 = 0.f, v1 = 0.f;
            if (ed < E && k0 < F) {
                const float* fr = feat + (size_t)ed * F;
                v0 = fr[k0];
                if (k0 + 1 < F) v1 = fr[k0 + 1];
            }
            buf[r * AW + kpl] = splitbf2p(make_float2(v0, v1));
        }
    };

    int ntiles = (E + 127) >> 7;
    int tile0 = blockIdx.x;
    if (tile0 < ntiles) stage(tile0, 0, Ab[0]);
    __syncthreads();

    for (int tile = tile0; tile < ntiles; tile += gridDim.x) {
        float acc[2][4][4];
        #pragma unroll
        for (int mf = 0; mf < 2; mf++)
            #pragma unroll
            for (int nf = 0; nf < 4; nf++)
                #pragma unroll
                for (int i = 0; i < 4; i++) acc[mf][nf][i] = 0.f;

        if (tid < 128) {
            int ed = tile * 128 + tid;
            srcs[tid] = (ed < E) ? ei[ed] : 0;
            dsts[tid] = (ed < E) ? ei[(size_t)E + ed] : 0;
        }
        // stage chunk1 (overlaps with mma chunk0 across warps)
        stage(tile, 1, Ab[1]);

        // mma over both chunks
        #pragma unroll
        for (int c = 0; c < 2; c++) {
            const uint2* buf = Ab[c];
            int kbase = c * CS;
            #pragma unroll
            for (int ks = 0; ks < 5; ks++) {
                int kpl = ks * 8;
                uint32_t bh[4][2], bl[4][2];
                #pragma unroll
                for (int nf = 0; nf < 4; nf++) {
                    int nn = wn * 32 + nf * 8 + g;
                    uint2 b0 = Bs[nn * WP + kbase + kpl + t];
                    uint2 b1 = Bs[nn * WP + kbase + kpl + t + 4];
                    bh[nf][0] = b0.x; bl[nf][0] = b0.y;
                    bh[nf][1] = b1.x; bl[nf][1] = b1.y;
                }
                #pragma unroll
                for (int mf = 0; mf < 2; mf++) {
                    int r = wg * 32 + mf * 16 + g;
                    uint2 a0 = buf[r * AW + kpl + t];
                    uint2 a1 = buf[(r + 8) * AW + kpl + t];
                    uint2 a2 = buf[r * AW + kpl + t + 4];
                    uint2 a3 = buf[(r + 8) * AW + kpl + t + 4];
                    #pragma unroll
                    for (int nf = 0; nf < 4; nf++)
                        mma3(acc[mf][nf], a0, a1, a2, a3,
                             bh[nf][0], bh[nf][1], bl[nf][0], bl[nf][1]);
                }
            }
            if (c == 0) {
                __syncthreads();  // chunk0 consumed; chunk1 staged
                int nt = tile + gridDim.x;
                if (nt < ntiles) stage(nt, 0, Ab[0]);  // prefetch next tile chunk0
            }
        }
        // epilogue: two 64-row halves via fs
        #pragma unroll
        for (int h = 0; h < 2; h++) {
            __syncthreads();
            if ((wg >> 1) == h) {
                int rbase = (wg & 1) * 32;
                #pragma unroll
                for (int mf = 0; mf < 2; mf++) {
                    int rb = rbase + mf * 16 + g;
                    #pragma unroll
                    for (int nf = 0; nf < 4; nf++) {
                        int col = wn * 32 + nf * 8 + 2 * t;
                        *(float2*)&fs[rb * 132 + col] =
                            make_float2(acc[mf][nf][0], acc[mf][nf][1]);
                        *(float2*)&fs[(rb + 8) * 132 + col] =
                            make_float2(acc[mf][nf][2], acc[mf][nf][3]);
                    }
                }
            }
            __syncthreads();
            int rl = tid >> 3, q = tid & 7;
            int ed = tile * 128 + h * 64 + rl;
            if (ed < E) {
                int s = srcs[h * 64 + rl], d = dsts[h * 64 + rl];
                const float4* xr = (const float4*)(xh + (size_t)s * 128);
                float4* ar = (float4*)(agg + (size_t)d * 128);
                #pragma unroll
                for (int i = 0; i < 4; i++) {
                    int c4 = q + 8 * i;
                    float4 f = *(float4*)&fs[rl * 132 + 4 * c4];
                    float4 xv = xr[c4];
                    atomicAdd(ar + c4,
                              make_float4(f.x * xv.x, f.y * xv.y, f.z * xv.z, f.w * xv.w));
                }
            }
        }
        __syncthreads();
    }
}

// ---------------- edge GEMM (F=21), single-chunk, 512 threads ----------------
__global__ __launch_bounds__(512, 1) void k_edgeS(
    const float* __restrict__ feat, const uint2* __restrict__ wpk,
    const int* __restrict__ ei, const float* __restrict__ xh,
    float* __restrict__ agg, int E) {
    constexpr int F = 21;
    constexpr int WP = 20;
    extern __shared__ uint2 shu[];
    uint2* Bs  = shu;
    uint2* As2 = shu + 128 * WP;
    float* fs = (float*)(As2 + 128 * WP);
    int* srcs = (int*)(fs + 64 * 132);
    int* dsts = srcs + 128;

    int tid = threadIdx.x, w = tid >> 5, lane = tid & 31, g = lane >> 2, t = lane & 3;
    int wg = w >> 2, wn = w & 3;

    for (int i = tid; i < 128 * WP; i += 512) Bs[i] = wpk[i];

    int ntiles = (E + 127) >> 7;
    for (int tile = blockIdx.x; tile < ntiles; tile += gridDim.x) {
        float acc[2][4][4];
        #pragma unroll
        for (int mf = 0; mf < 2; mf++)
            #pragma unroll
            for (int nf = 0; nf < 4; nf++)
                #pragma unroll
                for (int i = 0; i < 4; i++) acc[mf][nf][i] = 0.f;

        __syncthreads();
        if (tid < 128) {
            int ed = tile * 128 + tid;
            srcs[tid] = (ed < E) ? ei[ed] : 0;
            dsts[tid] = (ed < E) ? ei[(size_t)E + ed] : 0;
        }
        for (int i = tid; i < 128 * WP; i += 512) {
            int r = i / WP, kp = i - r * WP;
            int ed = tile * 128 + r;
            int k0 = 2 * kp;
            float v0 = 0.f, v1 = 0.f;
            if (ed < E && k0 < F) {
                const float* fr = feat + (size_t)ed * F;
                v0 = fr[k0];
                if (k0 + 1 < F) v1 = fr[k0 + 1];
            }
            As2[r * WP + kp] = splitbf2p(make_float2(v0, v1));
        }
        __syncthreads();
        #pragma unroll
        for (int ks = 0; ks < 2; ks++) {
            int kp0 = ks * 8;
            uint32_t bh[4][2], bl[4][2];
            #pragma unroll
            for (int nf = 0; nf < 4; nf++) {
                int nn = wn * 32 + nf * 8 + g;
                uint2 b0 = Bs[nn * WP + kp0 + t];
                uint2 b1 = Bs[nn * WP + kp0 + t + 4];
                bh[nf][0] = b0.x; bl[nf][0] = b0.y;
                bh[nf][1] = b1.x; bl[nf][1] = b1.y;
            }
            #pragma unroll
            for (int mf = 0; mf < 2; mf++) {
                int r = wg * 32 + mf * 16 + g;
                uint2 a0 = As2[r * WP + kp0 + t];
                uint2 a1 = As2[(r + 8) * WP + kp0 + t];
                uint2 a2 = As2[r * WP + kp0 + t + 4];
                uint2 a3 = As2[(r + 8) * WP + kp0 + t + 4];
                #pragma unroll
                for (int nf = 0; nf < 4; nf++)
                    mma3(acc[mf][nf], a0, a1, a2, a3,
                         bh[nf][0], bh[nf][1], bl[nf][0], bl[nf][1]);
            }
        }
        #pragma unroll
        for (int h = 0; h < 2; h++) {
            __syncthreads();
            if ((wg >> 1) == h) {
                int rbase = (wg & 1) * 32;
                #pragma unroll
                for (int mf = 0; mf < 2; mf++) {
                    int rb = rbase + mf * 16 + g;
                    #pragma unroll
                    for (int nf = 0; nf < 4; nf++) {
                        int col = wn * 32 + nf * 8 + 2 * t;
                        *(float2*)&fs[rb * 132 + col] =
                            make_float2(acc[mf][nf][0], acc[mf][nf][1]);
                        *(float2*)&fs[(rb + 8) * 132 + col] =
                            make_float2(acc[mf][nf][2], acc[mf][nf][3]);
                    }
                }
            }
            __syncthreads();
            int rl = tid >> 3, q = tid & 7;
            int ed = tile * 128 + h * 64 + rl;
            if (ed < E) {
                int s = srcs[h * 64 + rl], d = dsts[h * 64 + rl];
                const float4* xr = (const float4*)(xh + (size_t)s * 128);
                float4* ar = (float4*)(agg + (size_t)d * 128);
                #pragma unroll
                for (int i = 0; i < 4; i++) {
                    int c4 = q + 8 * i;
                    float4 f = *(float4*)&fs[rl * 132 + 4 * c4];
                    float4 xv = xr[c4];
                    atomicAdd(ar + c4,
                              make_float4(f.x * xv.x, f.y * xv.y, f.z * xv.z, f.w * xv.w));
                }
            }
        }
    }
}

// ---------------- GraphNorm pieces ----------------
__global__ void k_gsum(const float* __restrict__ h, const int* __restrict__ batch, int n) {
    int idx = blockIdx.x * blockDim.x + threadIdx.x;
    if (idx >= n * HH) return;
    int i = idx >> 7, c = idx & 127;
    int g = batch[i];
    if (c == 0) atomicAdd(&g_gcnt[g], 1.f);
    atomicAdd(&g_gsum[g * HH + c], h[idx]);
}

__global__ void k_center(const float* __restrict__ h, const int* __restrict__ batch,
                         const float* __restrict__ ms, int n) {
    int idx = blockIdx.x * blockDim.x + threadIdx.x;
    if (idx >= n * HH) return;
    int i = idx >> 7, c = idx & 127;
    int g = batch[i];
    float cnt = g_gcnt[g]; if (cnt < 1.f) cnt = 1.f;
    float mean = g_gsum[g * HH + c] / cnt;
    float o = h[idx] - mean * ms[c];
    g_on[idx] = o;
    atomicAdd(&g_gsq[g * HH + c], o * o);
}

__global__ void k_norm(const int* __restrict__ batch,
                       const float* __restrict__ w, const float* __restrict__ b, int n) {
    int idx = blockIdx.x * blockDim.x + threadIdx.x;
    if (idx >= n * HH) return;
    int i = idx >> 7, c = idx & 127;
    int g = batch[i];
    float cnt = g_gcnt[g]; if (cnt < 1.f) cnt = 1.f;
    float var = g_gsq[g * HH + c] / cnt;
    g_on[idx] = w[c] * g_on[idx] * rsqrtf(var + 1e-5f) + b[c];
}

// ---------------- launch ----------------
extern "C" void kernel_launch(void* const* d_in, const int* in_sizes, int n_in,
                              void* d_out, int out_size) {
    const float* x          = (const float*)d_in[0];
    const float* feature1   = (const float*)d_in[1];
    const float* feature2   = (const float*)d_in[2];
    const int*   edge_index = (const int*)d_in[3];
    const int*   batch      = (const int*)d_in[4];
    const float* lin_w        = (const float*)d_in[5];
    const float* lin_b        = (const float*)d_in[6];
    const float* f1_w1        = (const float*)d_in[7];
    const float* f1_w2        = (const float*)d_in[8];
    const float* f2_w1        = (const float*)d_in[9];
    const float* f2_w2        = (const float*)d_in[10];
    const float* conv1_rel_w  = (const float*)d_in[11];
    const float* conv1_rel_b  = (const float*)d_in[12];
    const float* conv1_root_w = (const float*)d_in[13];
    const float* conv2_rel_w  = (const float*)d_in[14];
    const float* conv2_rel_b  = (const float*)d_in[15];
    const float* conv2_root_w = (const float*)d_in[16];
    const float* lin1_w       = (const float*)d_in[17];
    const float* lin1_b       = (const float*)d_in[18];
    const float* lin2_w       = (const float*)d_in[19];
    const float* lin2_b       = (const float*)d_in[20];
    const float* lincat_w     = (const float*)d_in[21];
    const float* lincat_b     = (const float*)d_in[22];
    const float* norm_w       = (const float*)d_in[23];
    const float* norm_b       = (const float*)d_in[24];
    const float* norm_ms      = (const float*)d_in[25];
    const float* lins_w       = (const float*)d_in[26];
    const float* lins_b       = (const float*)d_in[27];
    const float* final_w      = (const float*)d_in[28];
    const float* final_b      = (const float*)d_in[29];

    int N_ = in_sizes[0] / HH;
    int E_ = in_sizes[3] / 2;

    static float *p_xh = nullptr, *p_agg1, *p_agg2, *p_c, *p_ha, *p_hb, *p_on;
    static uint2 *p_wa, *p_wb;
    if (!p_xh) {
        cudaGetSymbolAddress((void**)&p_xh,   g_xh);
        cudaGetSymbolAddress((void**)&p_agg1, g_agg1);
        cudaGetSymbolAddress((void**)&p_agg2, g_agg2);
        cudaGetSymbolAddress((void**)&p_c,    g_c);
        cudaGetSymbolAddress((void**)&p_ha,   g_ha);
        cudaGetSymbolAddress((void**)&p_hb,   g_hb);
        cudaGetSymbolAddress((void**)&p_on,   g_on);
        cudaGetSymbolAddress((void**)&p_wa,   g_w12a);
        cudaGetSymbolAddress((void**)&p_wb,   g_w12b);
    }

    const int sme1 = (128 * 84 + 2 * 128 * 44) * 8 + 64 * 132 * 4 + 1024;  // 210,944 B
    const int sme2 = 2 * 128 * 20 * 8 + 64 * 132 * 4 + 1024;               // 75,776 B
    const int smg  = 2 * 128 * 68 * 8 + 256;                               // 139,520 B
    static bool attr_done = false;
    if (!attr_done) {
        cudaFuncSetAttribute(k_edgeP, cudaFuncAttributeMaxDynamicSharedMemorySize, sme1);
        cudaFuncSetAttribute(k_edgeS, cudaFuncAttributeMaxDynamicSharedMemorySize, sme2);
        cudaFuncSetAttribute(k_gemmT<false, true, false>,  cudaFuncAttributeMaxDynamicSharedMemorySize, smg);
        cudaFuncSetAttribute(k_gemmT<true, false, false>,  cudaFuncAttributeMaxDynamicSharedMemorySize, smg);
        cudaFuncSetAttribute(k_gemmT<true, false, true>,   cudaFuncAttributeMaxDynamicSharedMemorySize, smg);
        cudaFuncSetAttribute(k_gemmT<false, true, true>,   cudaFuncAttributeMaxDynamicSharedMemorySize, smg);
        cudaFuncSetAttribute(k_gemmT<false, false, false>, cudaFuncAttributeMaxDynamicSharedMemorySize, smg);
        attr_done = true;
    }

    int NH_ = N_ * HH;
    int gZ = (NH_ + 255) / 256;
    int gB = (N_ + 127) / 128;

    // launch order: index 3 (ncu-captured) = k_edgeP (dominant kernel)
    k_w12pack<147, 84><<<128, 84>>>(f1_w1, f1_w2, p_wa);                                  // 0
    k_zero<<<gZ, 256>>>(0, NH_);                                                          // 1
    k_gemmT<false, true, false><<<gB, 512, smg>>>(x, lin_w, nullptr, nullptr, lin_b, nullptr, p_xh, N_);  // 2
    k_edgeP<<<148, 512, sme1>>>(feature1, p_wa, edge_index, p_xh, p_agg1, E_);            // 3
    k_w12pack<21, 20><<<128, 20>>>(f2_w1, f2_w2, p_wb);                                   // 4
    k_zero<<<gZ, 256>>>(1, NH_);                                                          // 5
    k_edgeS<<<296, 512, sme2>>>(feature2, p_wb, edge_index, p_xh, p_agg2, E_);            // 6

    // conv1 / lin1
    k_gemmT<true, false, false><<<gB, 512, smg>>>(p_agg1, conv1_rel_w, p_xh, conv1_root_w, conv1_rel_b, nullptr, p_c, N_);
    k_gemmT<false, true, false><<<gB, 512, smg>>>(p_c, lin1_w, nullptr, nullptr, lin1_b, nullptr, p_agg1, N_);
    // conv2 / lin2
    k_gemmT<true, false, false><<<gB, 512, smg>>>(p_agg2, conv2_rel_w, p_xh, conv2_root_w, conv2_rel_b, nullptr, p_c, N_);
    k_gemmT<false, true, false><<<gB, 512, smg>>>(p_c, lin2_w, nullptr, nullptr, lin2_b, nullptr, p_agg2, N_);

    // h = cat(h1,h2) @ lincat + b + xh
    k_gemmT<true, false, true><<<gB, 512, smg>>>(p_agg1, lincat_w, p_agg2, lincat_w + HH * HH, lincat_b, p_xh, p_ha, N_);

    // residual lins: h = swish(h@W+b) + h
    k_gemmT<false, true, true><<<gB, 512, smg>>>(p_ha, lins_w,               nullptr, nullptr, lins_b,          p_ha, p_hb, N_);
    k_gemmT<false, true, true><<<gB, 512, smg>>>(p_hb, lins_w + 1 * HH * HH, nullptr, nullptr, lins_b + 1 * HH, p_hb, p_ha, N_);
    k_gemmT<false, true, true><<<gB, 512, smg>>>(p_ha, lins_w + 2 * HH * HH, nullptr, nullptr, lins_b + 2 * HH, p_ha, p_hb, N_);

    // GraphNorm
    k_zero<<<(GG * HH + 255) / 256, 256>>>(2, NH_);
    k_gsum<<<gZ, 256>>>(p_hb, batch, N_);
    k_center<<<gZ, 256>>>(p_hb, batch, norm_ms, N_);
    k_norm<<<gZ, 256>>>(batch, norm_w, norm_b, N_);

    // final projection
    k_gemmT<false, false, false><<<gB, 512, smg>>>(p_on, final_w, nullptr, nullptr, final_b, nullptr, (float*)d_out, N_);
}

// round 9
// speedup vs baseline: 1.9523x; 1.1975x over previous
#include <cuda_runtime.h>
#include <cuda_bf16.h>
#include <cstdint>
#include <math.h>

#define HH 128
#define GG 512
#define MAXN 50000
#define NHH (MAXN * HH)

// ---------------- device scratch ----------------
__device__ float g_xh[NHH];
__device__ float g_agg1[NHH];
__device__ float g_agg2[NHH];
__device__ float g_c[NHH];
__device__ float g_ha[NHH];
__device__ float g_hb[NHH];
__device__ float g_on[NHH];
__device__ float g_gsum[GG * HH];
__device__ float g_gsq[GG * HH];
__device__ float g_gcnt[GG];
__device__ uint2 g_w12a[128 * 84];       // packed split-bf16 W12 (feature1)
__device__ uint2 g_w12b[128 * 20];       // (feature2)
__device__ uint2 g_wpk[13 * 128 * 68];   // packed node weights

// ---------------- bf16 split helpers ----------------
__device__ __forceinline__ uint2 splitbf2p(float2 v) {
    __nv_bfloat162 h = __float22bfloat162_rn(v);
    float2 hv = __bfloat1622float2(h);
    __nv_bfloat162 l = __float22bfloat162_rn(make_float2(v.x - hv.x, v.y - hv.y));
    uint2 r;
    r.x = *reinterpret_cast<uint32_t*>(&h);
    r.y = *reinterpret_cast<uint32_t*>(&l);
    return r;
}

__device__ __forceinline__ void mma16(float* d, uint32_t a0, uint32_t a1, uint32_t a2,
                                      uint32_t a3, uint32_t b0, uint32_t b1) {
    asm volatile(
        "mma.sync.aligned.m16n8k16.row.col.f32.bf16.bf16.f32 "
        "{%0,%1,%2,%3}, {%4,%5,%6,%7}, {%8,%9}, {%0,%1,%2,%3};\n"
        : "+f"(d[0]), "+f"(d[1]), "+f"(d[2]), "+f"(d[3])
        : "r"(a0), "r"(a1), "r"(a2), "r"(a3), "r"(b0), "r"(b1));
}

__device__ __forceinline__ void mma3(float* d, const uint2& a0, const uint2& a1,
                                     const uint2& a2, const uint2& a3,
                                     uint32_t bh0, uint32_t bh1, uint32_t bl0, uint32_t bl1) {
    mma16(d, a0.x, a1.x, a2.x, a3.x, bh0, bh1);
    mma16(d, a0.x, a1.x, a2.x, a3.x, bl0, bl1);
    mma16(d, a0.y, a1.y, a2.y, a3.y, bh0, bh1);
}

// ---------------- misc kernels ----------------
__global__ void k_zero(int sel, int n) {
    int i = blockIdx.x * blockDim.x + threadIdx.x;
    if (sel == 0) { if (i < n) g_agg1[i] = 0.f; }
    else if (sel == 1) { if (i < n) g_agg2[i] = 0.f; }
    else {
        if (i < GG * HH) { g_gsum[i] = 0.f; g_gsq[i] = 0.f; }
        if (i < GG) g_gcnt[i] = 0.f;
    }
}

template <int F, int WP>
__global__ void k_w12pack(const float* __restrict__ W1, const float* __restrict__ W2,
                          uint2* __restrict__ out) {
    int n = blockIdx.x;
    int kp = threadIdx.x;
    if (kp >= WP) return;
    int k0 = 2 * kp, k1 = 2 * kp + 1;
    float a0 = 0.f, a1 = 0.f;
    for (int m = 0; m < 64; m++) {
        float w2 = W2[m * 128 + n];
        if (k0 < F) a0 += W1[k0 * 64 + m] * w2;
        if (k1 < F) a1 += W1[k1 * 64 + m] * w2;
    }
    out[n * WP + kp] = splitbf2p(make_float2(a0, a1));
}

// pack 13 [128,128] node weight matrices, n-major kpairs, width 68
__global__ void k_wpackAll(const float* p0, const float* p1, const float* p2,
                           const float* p3, const float* p4, const float* p5,
                           const float* p6, const float* p7, const float* p8,
                           const float* p9, const float* p10, const float* p11,
                           const float* p12) {
    const float* srcs[13] = {p0, p1, p2, p3, p4, p5, p6, p7, p8, p9, p10, p11, p12};
    const float* W = srcs[blockIdx.x];
    uint2* dst = g_wpk + blockIdx.x * (128 * 68);
    int n = threadIdx.x;
    for (int kp = 0; kp < 64; kp++) {
        float w0 = W[(2 * kp) * 128 + n];
        float w1 = W[(2 * kp + 1) * 128 + n];
        dst[n * 68 + kp] = splitbf2p(make_float2(w0, w1));
    }
}

// ---------------- old-style node GEMM (512 thr, m128) — used only for xh ----------------
template <bool DUAL, bool SW, bool RES>
__global__ __launch_bounds__(512, 1) void k_gemmT(
    const float* __restrict__ A, const float* __restrict__ Wa,
    const float* __restrict__ B, const float* __restrict__ Wb,
    const float* __restrict__ bias, const float* __restrict__ R,
    float* __restrict__ out, int n) {
    constexpr int WW = 68;
    extern __shared__ uint2 shu[];
    uint2* Ws  = shu;
    uint2* As2 = shu + 128 * WW;
    int tid = threadIdx.x, w = tid >> 5, lane = tid & 31, g = lane >> 2, t = lane & 3;
    int wg = w >> 2, wn = w & 3;
    int r0 = blockIdx.x * 128;

    float acc[2][4][4];
    #pragma unroll
    for (int mf = 0; mf < 2; mf++)
        #pragma unroll
        for (int nf = 0; nf < 4; nf++)
            #pragma unroll
            for (int i = 0; i < 4; i++) acc[mf][nf][i] = 0.f;

    const int NPASS = DUAL ? 2 : 1;
    for (int p = 0; p < NPASS; p++) {
        const float* Ain = p ? B : A;
        const float* Win = p ? Wb : Wa;
        __syncthreads();
        for (int i = tid; i < 128 * 64; i += 512) {
            int nn = i & 127, kp = i >> 7;
            float w0 = Win[(2 * kp) * 128 + nn];
            float w1 = Win[(2 * kp + 1) * 128 + nn];
            Ws[nn * WW + kp] = splitbf2p(make_float2(w0, w1));
        }
        for (int i = tid; i < 128 * 64; i += 512) {
            int r = i >> 6, kp = i & 63;
            int row = r0 + r;
            float2 v = (row < n) ? *(const float2*)(Ain + (size_t)row * 128 + 2 * kp)
                                 : make_float2(0.f, 0.f);
            As2[r * WW + kp] = splitbf2p(v);
        }
        __syncthreads();
        #pragma unroll
        for (int ks = 0; ks < 8; ks++) {
            int kp0 = ks * 8;
            uint32_t bh[4][2], bl[4][2];
            #pragma unroll
            for (int nf = 0; nf < 4; nf++) {
                int nn = wn * 32 + nf * 8 + g;
                uint2 b0 = Ws[nn * WW + kp0 + t];
                uint2 b1 = Ws[nn * WW + kp0 + t + 4];
                bh[nf][0] = b0.x; bl[nf][0] = b0.y;
                bh[nf][1] = b1.x; bl[nf][1] = b1.y;
            }
            #pragma unroll
            for (int mf = 0; mf < 2; mf++) {
                int r = wg * 32 + mf * 16 + g;
                uint2 a0 = As2[r * WW + kp0 + t];
                uint2 a1 = As2[(r + 8) * WW + kp0 + t];
                uint2 a2 = As2[r * WW + kp0 + t + 4];
                uint2 a3 = As2[(r + 8) * WW + kp0 + t + 4];
                #pragma unroll
                for (int nf = 0; nf < 4; nf++)
                    mma3(acc[mf][nf], a0, a1, a2, a3,
                         bh[nf][0], bh[nf][1], bl[nf][0], bl[nf][1]);
            }
        }
    }
    float2 bb[4];
    #pragma unroll
    for (int nf = 0; nf < 4; nf++) bb[nf] = *(const float2*)&bias[wn * 32 + nf * 8 + 2 * t];
    #pragma unroll
    for (int mf = 0; mf < 2; mf++) {
        #pragma unroll
        for (int half = 0; half < 2; half++) {
            int row = r0 + wg * 32 + mf * 16 + g + 8 * half;
            if (row < n) {
                #pragma unroll
                for (int nf = 0; nf < 4; nf++) {
                    int col = wn * 32 + nf * 8 + 2 * t;
                    float vx = acc[mf][nf][2 * half + 0] + bb[nf].x;
                    float vy = acc[mf][nf][2 * half + 1] + bb[nf].y;
                    if (SW) { vx = vx / (1.f + expf(-vx)); vy = vy / (1.f + expf(-vy)); }
                    if (RES) {
                        float2 rv = *(const float2*)&R[(size_t)row * 128 + col];
                        vx += rv.x; vy += rv.y;
                    }
                    *(float2*)&out[(size_t)row * 128 + col] = make_float2(vx, vy);
                }
            }
        }
    }
}

// ---------------- new node GEMM: 256 thr, m64 tile, B-frags from L1 (packed) ----------------
template <bool DUAL, bool SW, bool RES>
__global__ __launch_bounds__(256, 3) void k_gemm2(
    const float* __restrict__ A, const uint2* __restrict__ Wa,
    const float* __restrict__ B, const uint2* __restrict__ Wb,
    const float* __restrict__ bias, const float* __restrict__ R,
    float* __restrict__ out, int n) {
    constexpr int WW = 68;
    extern __shared__ uint2 shu[];
    uint2* As2 = shu;   // [64][68]
    int tid = threadIdx.x, w = tid >> 5, lane = tid & 31, g = lane >> 2, t = lane & 3;
    int wg = w >> 2, wn = w & 3;   // wg 0..1 (m), wn 0..3 (n)
    int r0 = blockIdx.x * 64;

    float acc[2][4][4];
    #pragma unroll
    for (int mf = 0; mf < 2; mf++)
        #pragma unroll
        for (int nf = 0; nf < 4; nf++)
            #pragma unroll
            for (int i = 0; i < 4; i++) acc[mf][nf][i] = 0.f;

    const int NPASS = DUAL ? 2 : 1;
    for (int p = 0; p < NPASS; p++) {
        const float* Ain = p ? B : A;
        const uint2* Wp = p ? Wb : Wa;
        __syncthreads();
        for (int i = tid; i < 64 * 64; i += 256) {
            int r = i >> 6, kp = i & 63;
            int row = r0 + r;
            float2 v = (row < n) ? *(const float2*)(Ain + (size_t)row * 128 + 2 * kp)
                                 : make_float2(0.f, 0.f);
            As2[r * WW + kp] = splitbf2p(v);
        }
        __syncthreads();
        #pragma unroll
        for (int ks = 0; ks < 8; ks++) {
            int kp0 = ks * 8;
            uint32_t bh[4][2], bl[4][2];
            #pragma unroll
            for (int nf = 0; nf < 4; nf++) {
                int nn = wn * 32 + nf * 8 + g;
                uint2 b0 = __ldg(&Wp[nn * WW + kp0 + t]);
                uint2 b1 = __ldg(&Wp[nn * WW + kp0 + t + 4]);
                bh[nf][0] = b0.x; bl[nf][0] = b0.y;
                bh[nf][1] = b1.x; bl[nf][1] = b1.y;
            }
            #pragma unroll
            for (int mf = 0; mf < 2; mf++) {
                int r = wg * 32 + mf * 16 + g;
                uint2 a0 = As2[r * WW + kp0 + t];
                uint2 a1 = As2[(r + 8) * WW + kp0 + t];
                uint2 a2 = As2[r * WW + kp0 + t + 4];
                uint2 a3 = As2[(r + 8) * WW + kp0 + t + 4];
                #pragma unroll
                for (int nf = 0; nf < 4; nf++)
                    mma3(acc[mf][nf], a0, a1, a2, a3,
                         bh[nf][0], bh[nf][1], bl[nf][0], bl[nf][1]);
            }
        }
    }
    float2 bb[4];
    #pragma unroll
    for (int nf = 0; nf < 4; nf++) bb[nf] = *(const float2*)&bias[wn * 32 + nf * 8 + 2 * t];
    #pragma unroll
    for (int mf = 0; mf < 2; mf++) {
        #pragma unroll
        for (int half = 0; half < 2; half++) {
            int row = r0 + wg * 32 + mf * 16 + g + 8 * half;
            if (row < n) {
                #pragma unroll
                for (int nf = 0; nf < 4; nf++) {
                    int col = wn * 32 + nf * 8 + 2 * t;
                    float vx = acc[mf][nf][2 * half + 0] + bb[nf].x;
                    float vy = acc[mf][nf][2 * half + 1] + bb[nf].y;
                    if (SW) { vx = vx / (1.f + expf(-vx)); vy = vy / (1.f + expf(-vy)); }
                    if (RES) {
                        float2 rv = *(const float2*)&R[(size_t)row * 128 + col];
                        vx += rv.x; vy += rv.y;
                    }
                    *(float2*)&out[(size_t)row * 128 + col] = make_float2(vx, vy);
                }
            }
        }
    }
}

// ---------------- pipelined edge GEMM (F=147): LDG-early, 10 chunks x k16 ----------------
__global__ __launch_bounds__(512, 1) void k_edgeP(
    const float* __restrict__ feat, const uint2* __restrict__ wpk,
    const int* __restrict__ ei, const float* __restrict__ xh,
    float* __restrict__ agg, int E) {
    constexpr int WP = 84;   // B kpair width
    constexpr int AW = 12;   // A chunk buf width (8 kpairs + 4 pad)
    extern __shared__ uint2 shu[];
    uint2* Bs  = shu;                        // [128][84]
    uint2* Ab0 = shu + 128 * WP;             // [128][12]
    uint2* Ab1 = Ab0 + 128 * AW;             // [128][12]
    float* fs  = (float*)(Ab1 + 128 * AW);   // [64][132]
    int* srcs = (int*)(fs + 64 * 132);
    int* dsts = srcs + 128;

    int tid = threadIdx.x, w = tid >> 5, lane = tid & 31, g = lane >> 2, t = lane & 3;
    int wg = w >> 2, wn = w & 3;
    int lr = tid >> 2, t4 = tid & 3;   // ldg mapping: row, k-quarter

    for (int i = tid; i < 128 * WP; i += 512) Bs[i] = wpk[i];

    int ntiles = (E + 127) >> 7;

    float lf[4];
    // prologue: stage chunk0 of first tile
    if ((int)blockIdx.x < ntiles) {
        int ed = blockIdx.x * 128 + lr;
        const float* fr = feat + (size_t)ed * 147 + 4 * t4;
        #pragma unroll
        for (int j = 0; j < 4; j++) lf[j] = (ed < E) ? fr[j] : 0.f;
        uint2 u0 = splitbf2p(make_float2(lf[0], lf[1]));
        uint2 u1 = splitbf2p(make_float2(lf[2], lf[3]));
        uint4 pk = make_uint4(u0.x, u0.y, u1.x, u1.y);
        *(uint4*)&Ab0[lr * AW + 2 * t4] = pk;
    }
    __syncthreads();

    for (int tile = blockIdx.x; tile < ntiles; tile += gridDim.x) {
        float acc[2][4][4];
        #pragma unroll
        for (int mf = 0; mf < 2; mf++)
            #pragma unroll
            for (int nf = 0; nf < 4; nf++)
                #pragma unroll
                for (int i = 0; i < 4; i++) acc[mf][nf][i] = 0.f;

        if (tid < 128) {
            int ed = tile * 128 + tid;
            srcs[tid] = (ed < E) ? ei[ed] : 0;
            dsts[tid] = (ed < E) ? ei[(size_t)E + ed] : 0;
        }

        for (int c = 0; c < 10; c++) {
            uint2* cur = (c & 1) ? Ab1 : Ab0;
            uint2* nxt = (c & 1) ? Ab0 : Ab1;
            int nt = tile, nc = c + 1;
            if (nc == 10) { nt = tile + gridDim.x; nc = 0; }
            bool dl = (nt < ntiles);
            if (dl) {
                int ed = nt * 128 + lr;
                int kb = 16 * nc + 4 * t4;
                const float* fr = feat + (size_t)ed * 147 + kb;
                #pragma unroll
                for (int j = 0; j < 4; j++)
                    lf[j] = (ed < E && (kb + j) < 147) ? fr[j] : 0.f;
            }
            // mma on current chunk
            {
                int kbp = 8 * c;
                uint32_t bh[4][2], bl[4][2];
                #pragma unroll
                for (int nf = 0; nf < 4; nf++) {
                    int nn = wn * 32 + nf * 8 + g;
                    uint2 b0 = Bs[nn * WP + kbp + t];
                    uint2 b1 = Bs[nn * WP + kbp + t + 4];
                    bh[nf][0] = b0.x; bl[nf][0] = b0.y;
                    bh[nf][1] = b1.x; bl[nf][1] = b1.y;
                }
                #pragma unroll
                for (int mf = 0; mf < 2; mf++) {
                    int rr = wg * 32 + mf * 16 + g;
                    uint2 a0 = cur[rr * AW + t];
                    uint2 a1 = cur[(rr + 8) * AW + t];
                    uint2 a2 = cur[rr * AW + t + 4];
                    uint2 a3 = cur[(rr + 8) * AW + t + 4];
                    #pragma unroll
                    for (int nf = 0; nf < 4; nf++)
                        mma3(acc[mf][nf], a0, a1, a2, a3,
                             bh[nf][0], bh[nf][1], bl[nf][0], bl[nf][1]);
                }
            }
            if (dl) {
                uint2 u0 = splitbf2p(make_float2(lf[0], lf[1]));
                uint2 u1 = splitbf2p(make_float2(lf[2], lf[3]));
                uint4 pk = make_uint4(u0.x, u0.y, u1.x, u1.y);
                *(uint4*)&nxt[lr * AW + 2 * t4] = pk;
            }
            __syncthreads();
        }
        // epilogue: two 64-row halves via fs
        #pragma unroll
        for (int h = 0; h < 2; h++) {
            __syncthreads();
            if ((wg >> 1) == h) {
                int rbase = (wg & 1) * 32;
                #pragma unroll
                for (int mf = 0; mf < 2; mf++) {
                    int rb = rbase + mf * 16 + g;
                    #pragma unroll
                    for (int nf = 0; nf < 4; nf++) {
                        int col = wn * 32 + nf * 8 + 2 * t;
                        *(float2*)&fs[rb * 132 + col] =
                            make_float2(acc[mf][nf][0], acc[mf][nf][1]);
                        *(float2*)&fs[(rb + 8) * 132 + col] =
                            make_float2(acc[mf][nf][2], acc[mf][nf][3]);
                    }
                }
            }
            __syncthreads();
            int rl = tid >> 3, q = tid & 7;
            int ed = tile * 128 + h * 64 + rl;
            if (ed < E) {
                int s = srcs[h * 64 + rl], d = dsts[h * 64 + rl];
                const float4* xr = (const float4*)(xh + (size_t)s * 128);
                float4* ar = (float4*)(agg + (size_t)d * 128);
                #pragma unroll
                for (int i = 0; i < 4; i++) {
                    int c4 = q + 8 * i;
                    float4 f = *(float4*)&fs[rl * 132 + 4 * c4];
                    float4 xv = xr[c4];
                    atomicAdd(ar + c4,
                              make_float4(f.x * xv.x, f.y * xv.y, f.z * xv.z, f.w * xv.w));
                }
            }
        }
        __syncthreads();
    }
}

// ---------------- edge GEMM (F=21), single-chunk ----------------
__global__ __launch_bounds__(512, 1) void k_edgeS(
    const float* __restrict__ feat, const uint2* __restrict__ wpk,
    const int* __restrict__ ei, const float* __restrict__ xh,
    float* __restrict__ agg, int E) {
    constexpr int F = 21;
    constexpr int WP = 20;
    extern __shared__ uint2 shu[];
    uint2* Bs  = shu;
    uint2* As2 = shu + 128 * WP;
    float* fs = (float*)(As2 + 128 * WP);
    int* srcs = (int*)(fs + 64 * 132);
    int* dsts = srcs + 128;

    int tid = threadIdx.x, w = tid >> 5, lane = tid & 31, g = lane >> 2, t = lane & 3;
    int wg = w >> 2, wn = w & 3;

    for (int i = tid; i < 128 * WP; i += 512) Bs[i] = wpk[i];

    int ntiles = (E + 127) >> 7;
    for (int tile = blockIdx.x; tile < ntiles; tile += gridDim.x) {
        float acc[2][4][4];
        #pragma unroll
        for (int mf = 0; mf < 2; mf++)
            #pragma unroll
            for (int nf = 0; nf < 4; nf++)
                #pragma unroll
                for (int i = 0; i < 4; i++) acc[mf][nf][i] = 0.f;

        __syncthreads();
        if (tid < 128) {
            int ed = tile * 128 + tid;
            srcs[tid] = (ed < E) ? ei[ed] : 0;
            dsts[tid] = (ed < E) ? ei[(size_t)E + ed] : 0;
        }
        for (int i = tid; i < 128 * WP; i += 512) {
            int r = i / WP, kp = i - r * WP;
            int ed = tile * 128 + r;
            int k0 = 2 * kp;
            float v0 = 0.f, v1 = 0.f;
            if (ed < E && k0 < F) {
                const float* fr = feat + (size_t)ed * F;
                v0 = fr[k0];
                if (k0 + 1 < F) v1 = fr[k0 + 1];
            }
            As2[r * WP + kp] = splitbf2p(make_float2(v0, v1));
        }
        __syncthreads();
        #pragma unroll
        for (int ks = 0; ks < 2; ks++) {
            int kp0 = ks * 8;
            uint32_t bh[4][2], bl[4][2];
            #pragma unroll
            for (int nf = 0; nf < 4; nf++) {
                int nn = wn * 32 + nf * 8 + g;
                uint2 b0 = Bs[nn * WP + kp0 + t];
                uint2 b1 = Bs[nn * WP + kp0 + t + 4];
                bh[nf][0] = b0.x; bl[nf][0] = b0.y;
                bh[nf][1] = b1.x; bl[nf][1] = b1.y;
            }
            #pragma unroll
            for (int mf = 0; mf < 2; mf++) {
                int r = wg * 32 + mf * 16 + g;
                uint2 a0 = As2[r * WP + kp0 + t];
                uint2 a1 = As2[(r + 8) * WP + kp0 + t];
                uint2 a2 = As2[r * WP + kp0 + t + 4];
                uint2 a3 = As2[(r + 8) * WP + kp0 + t + 4];
                #pragma unroll
                for (int nf = 0; nf < 4; nf++)
                    mma3(acc[mf][nf], a0, a1, a2, a3,
                         bh[nf][0], bh[nf][1], bl[nf][0], bl[nf][1]);
            }
        }
        #pragma unroll
        for (int h = 0; h < 2; h++) {
            __syncthreads();
            if ((wg >> 1) == h) {
                int rbase = (wg & 1) * 32;
                #pragma unroll
                for (int mf = 0; mf < 2; mf++) {
                    int rb = rbase + mf * 16 + g;
                    #pragma unroll
                    for (int nf = 0; nf < 4; nf++) {
                        int col = wn * 32 + nf * 8 + 2 * t;
                        *(float2*)&fs[rb * 132 + col] =
                            make_float2(acc[mf][nf][0], acc[mf][nf][1]);
                        *(float2*)&fs[(rb + 8) * 132 + col] =
                            make_float2(acc[mf][nf][2], acc[mf][nf][3]);
                    }
                }
            }
            __syncthreads();
            int rl = tid >> 3, q = tid & 7;
            int ed = tile * 128 + h * 64 + rl;
            if (ed < E) {
                int s = srcs[h * 64 + rl], d = dsts[h * 64 + rl];
                const float4* xr = (const float4*)(xh + (size_t)s * 128);
                float4* ar = (float4*)(agg + (size_t)d * 128);
                #pragma unroll
                for (int i = 0; i < 4; i++) {
                    int c4 = q + 8 * i;
                    float4 f = *(float4*)&fs[rl * 132 + 4 * c4];
                    float4 xv = xr[c4];
                    atomicAdd(ar + c4,
                              make_float4(f.x * xv.x, f.y * xv.y, f.z * xv.z, f.w * xv.w));
                }
            }
        }
    }
}

// ---------------- GraphNorm pieces ----------------
__global__ void k_gsum(const float* __restrict__ h, const int* __restrict__ batch, int n) {
    int idx = blockIdx.x * blockDim.x + threadIdx.x;
    if (idx >= n * HH) return;
    int i = idx >> 7, c = idx & 127;
    int g = batch[i];
    if (c == 0) atomicAdd(&g_gcnt[g], 1.f);
    atomicAdd(&g_gsum[g * HH + c], h[idx]);
}

__global__ void k_center(const float* __restrict__ h, const int* __restrict__ batch,
                         const float* __restrict__ ms, int n) {
    int idx = blockIdx.x * blockDim.x + threadIdx.x;
    if (idx >= n * HH) return;
    int i = idx >> 7, c = idx & 127;
    int g = batch[i];
    float cnt = g_gcnt[g]; if (cnt < 1.f) cnt = 1.f;
    float mean = g_gsum[g * HH + c] / cnt;
    float o = h[idx] - mean * ms[c];
    g_on[idx] = o;
    atomicAdd(&g_gsq[g * HH + c], o * o);
}

__global__ void k_norm(const int* __restrict__ batch,
                       const float* __restrict__ w, const float* __restrict__ b, int n) {
    int idx = blockIdx.x * blockDim.x + threadIdx.x;
    if (idx >= n * HH) return;
    int i = idx >> 7, c = idx & 127;
    int g = batch[i];
    float cnt = g_gcnt[g]; if (cnt < 1.f) cnt = 1.f;
    float var = g_gsq[g * HH + c] / cnt;
    g_on[idx] = w[c] * g_on[idx] * rsqrtf(var + 1e-5f) + b[c];
}

// ---------------- launch ----------------
extern "C" void kernel_launch(void* const* d_in, const int* in_sizes, int n_in,
                              void* d_out, int out_size) {
    const float* x          = (const float*)d_in[0];
    const float* feature1   = (const float*)d_in[1];
    const float* feature2   = (const float*)d_in[2];
    const int*   edge_index = (const int*)d_in[3];
    const int*   batch      = (const int*)d_in[4];
    const float* lin_w        = (const float*)d_in[5];
    const float* lin_b        = (const float*)d_in[6];
    const float* f1_w1        = (const float*)d_in[7];
    const float* f1_w2        = (const float*)d_in[8];
    const float* f2_w1        = (const float*)d_in[9];
    const float* f2_w2        = (const float*)d_in[10];
    const float* conv1_rel_w  = (const float*)d_in[11];
    const float* conv1_rel_b  = (const float*)d_in[12];
    const float* conv1_root_w = (const float*)d_in[13];
    const float* conv2_rel_w  = (const float*)d_in[14];
    const float* conv2_rel_b  = (const float*)d_in[15];
    const float* conv2_root_w = (const float*)d_in[16];
    const float* lin1_w       = (const float*)d_in[17];
    const float* lin1_b       = (const float*)d_in[18];
    const float* lin2_w       = (const float*)d_in[19];
    const float* lin2_b       = (const float*)d_in[20];
    const float* lincat_w     = (const float*)d_in[21];
    const float* lincat_b     = (const float*)d_in[22];
    const float* norm_w       = (const float*)d_in[23];
    const float* norm_b       = (const float*)d_in[24];
    const float* norm_ms      = (const float*)d_in[25];
    const float* lins_w       = (const float*)d_in[26];
    const float* lins_b       = (const float*)d_in[27];
    const float* final_w      = (const float*)d_in[28];
    const float* final_b      = (const float*)d_in[29];

    int N_ = in_sizes[0] / HH;
    int E_ = in_sizes[3] / 2;

    static float *p_xh = nullptr, *p_agg1, *p_agg2, *p_c, *p_ha, *p_hb, *p_on;
    static uint2 *p_wa, *p_wb, *p_wpk;
    if (!p_xh) {
        cudaGetSymbolAddress((void**)&p_xh,   g_xh);
        cudaGetSymbolAddress((void**)&p_agg1, g_agg1);
        cudaGetSymbolAddress((void**)&p_agg2, g_agg2);
        cudaGetSymbolAddress((void**)&p_c,    g_c);
        cudaGetSymbolAddress((void**)&p_ha,   g_ha);
        cudaGetSymbolAddress((void**)&p_hb,   g_hb);
        cudaGetSymbolAddress((void**)&p_on,   g_on);
        cudaGetSymbolAddress((void**)&p_wa,   g_w12a);
        cudaGetSymbolAddress((void**)&p_wb,   g_w12b);
        cudaGetSymbolAddress((void**)&p_wpk,  g_wpk);
    }

    const int sme1 = 128 * 84 * 8 + 2 * 128 * 12 * 8 + 64 * 132 * 4 + 1024;  // 145,408
    const int sme2 = 2 * 128 * 20 * 8 + 64 * 132 * 4 + 1024;                 // 75,776
    const int smg  = 2 * 128 * 68 * 8 + 256;                                 // 139,520
    const int smg2 = 64 * 68 * 8 + 128;                                      // 34,944
    static bool attr_done = false;
    if (!attr_done) {
        cudaFuncSetAttribute(k_edgeP, cudaFuncAttributeMaxDynamicSharedMemorySize, sme1);
        cudaFuncSetAttribute(k_edgeS, cudaFuncAttributeMaxDynamicSharedMemorySize, sme2);
        cudaFuncSetAttribute(k_gemmT<false, true, false>, cudaFuncAttributeMaxDynamicSharedMemorySize, smg);
        cudaFuncSetAttribute(k_gemm2<true, false, false>,  cudaFuncAttributeMaxDynamicSharedMemorySize, smg2);
        cudaFuncSetAttribute(k_gemm2<false, true, false>,  cudaFuncAttributeMaxDynamicSharedMemorySize, smg2);
        cudaFuncSetAttribute(k_gemm2<true, false, true>,   cudaFuncAttributeMaxDynamicSharedMemorySize, smg2);
        cudaFuncSetAttribute(k_gemm2<false, true, true>,   cudaFuncAttributeMaxDynamicSharedMemorySize, smg2);
        cudaFuncSetAttribute(k_gemm2<false, false, false>, cudaFuncAttributeMaxDynamicSharedMemorySize, smg2);
        attr_done = true;
    }

    int NH_ = N_ * HH;
    int gZ = (NH_ + 255) / 256;
    int gB128 = (N_ + 127) / 128;
    int gB64 = (N_ + 63) / 64;
    const int WMAT = 128 * 68;

    // launch order: index 3 = k_edgeP (profiling target)
    k_w12pack<147, 84><<<128, 84>>>(f1_w1, f1_w2, p_wa);                                  // 0
    k_zero<<<gZ, 256>>>(0, NH_);                                                          // 1
    k_gemmT<false, true, false><<<gB128, 512, smg>>>(x, lin_w, nullptr, nullptr, lin_b, nullptr, p_xh, N_);  // 2
    k_edgeP<<<148, 512, sme1>>>(feature1, p_wa, edge_index, p_xh, p_agg1, E_);            // 3
    k_wpackAll<<<13, 128>>>(lin_w, conv1_rel_w, conv1_root_w, conv2_rel_w, conv2_root_w,
                            lin1_w, lin2_w, lincat_w, lincat_w + HH * HH,
                            lins_w, lins_w + HH * HH, lins_w + 2 * HH * HH, final_w);     // 4
    k_w12pack<21, 20><<<128, 20>>>(f2_w1, f2_w2, p_wb);                                   // 5
    k_zero<<<gZ, 256>>>(1, NH_);                                                          // 6
    k_edgeS<<<296, 512, sme2>>>(feature2, p_wb, edge_index, p_xh, p_agg2, E_);            // 7

    // conv1 / lin1
    k_gemm2<true, false, false><<<gB64, 256, smg2>>>(p_agg1, p_wpk + 1 * WMAT, p_xh, p_wpk + 2 * WMAT, conv1_rel_b, nullptr, p_c, N_);
    k_gemm2<false, true, false><<<gB64, 256, smg2>>>(p_c, p_wpk + 5 * WMAT, nullptr, nullptr, lin1_b, nullptr, p_agg1, N_);
    // conv2 / lin2
    k_gemm2<true, false, false><<<gB64, 256, smg2>>>(p_agg2, p_wpk + 3 * WMAT, p_xh, p_wpk + 4 * WMAT, conv2_rel_b, nullptr, p_c, N_);
    k_gemm2<false, true, false><<<gB64, 256, smg2>>>(p_c, p_wpk + 6 * WMAT, nullptr, nullptr, lin2_b, nullptr, p_agg2, N_);

    // h = cat(h1,h2) @ lincat + b + xh
    k_gemm2<true, false, true><<<gB64, 256, smg2>>>(p_agg1, p_wpk + 7 * WMAT, p_agg2, p_wpk + 8 * WMAT, lincat_b, p_xh, p_ha, N_);

    // residual lins
    k_gemm2<false, true, true><<<gB64, 256, smg2>>>(p_ha, p_wpk + 9 * WMAT,  nullptr, nullptr, lins_b,          p_ha, p_hb, N_);
    k_gemm2<false, true, true><<<gB64, 256, smg2>>>(p_hb, p_wpk + 10 * WMAT, nullptr, nullptr, lins_b + HH,     p_hb, p_ha, N_);
    k_gemm2<false, true, true><<<gB64, 256, smg2>>>(p_ha, p_wpk + 11 * WMAT, nullptr, nullptr, lins_b + 2 * HH, p_ha, p_hb, N_);

    // GraphNorm
    k_zero<<<(GG * HH + 255) / 256, 256>>>(2, NH_);
    k_gsum<<<gZ, 256>>>(p_hb, batch, N_);
    k_center<<<gZ, 256>>>(p_hb, batch, norm_ms, N_);
    k_norm<<<gZ, 256>>>(batch, norm_w, norm_b, N_);

    // final projection
    k_gemm2<false, false, false><<<gB64, 256, smg2>>>(p_on, p_wpk + 12 * WMAT, nullptr, nullptr, final_b, nullptr, (float*)d_out, N_);
}